// round 11
// baseline (speedup 1.0000x reference)
#include <cuda_runtime.h>
#include <cuda_bf16.h>
#include <cstdint>

#define NB 8
#define NC 10
#define NH 192
#define NW 192
#define HW (NH*NW)
#define CHW (NC*HW)

// ---------------- k2 geometry ----------------
#define TILE_W 32
#define TILE_H 4
#define TROWP 40              /* tile row floats, base gx = x0-4 */
#define TCI_STRIDE 240        /* 6 rows x 40 */
#define TILE_CHUNKS 600       /* float4 chunks per 10-ch tile */

// weight panels: [16 outs x 168 K-halves] bf16, row stride 84 words (bank-conflict-free)
#define KPW 84
#define PANEL_B 5376          /* 16*168*2 bytes */

// smem byte layout
#define SM_PANELS 0           /* 8 local panels = 43008 */
#define SM_T0 43008
#define SM_T1 52608
#define SM_T2 62208
#define SM_MSG 71808          /* 128 x 12 floats = 6144 */
#define SM_PAR 77952          /* 304 floats = 1216 */
#define SMEM_BYTES (SM_PAR + 1216)

// param offsets (floats)
#define P_GD 0
#define P_BED 10
#define P_GC 20
#define P_BEC 30
#define P_GG 40
#define P_BEG 50
#define P_WG 60
#define P_BG 100
#define P_WC 102

// ---------------- scratch (static device globals; no allocation) ----------------
__device__ __align__(16) float g_a1[NB*CHW];
__device__ __align__(16) float g_a2[NB*CHW];
__device__ __align__(16) float g_pm[6*NB*CHW];
// 12 global panels: s=0..5 {wdt0,wdt1,wcu0,wcu1,wcl0,wcl1} x {hi,lo}
__device__ __align__(16) unsigned short g_wp[12*16*168];

__device__ __forceinline__ float sigmoidf_(float x){ return 1.0f/(1.0f+expf(-x)); }
__device__ __forceinline__ float4 f4fma(float s, float4 v, float4 a){
    return make_float4(fmaf(s,v.x,a.x), fmaf(s,v.y,a.y), fmaf(s,v.z,a.z), fmaf(s,v.w,a.w));
}
__device__ __forceinline__ float4 f4s(float s){ return make_float4(s,s,s,s); }

__device__ __forceinline__ uint32_t smem_to_u32(const void* p) {
    uint32_t a;
    asm("{ .reg .u64 t; cvta.to.shared.u64 t, %1; cvt.u32.u64 %0, t; }" : "=r"(a) : "l"(p));
    return a;
}
#define CP_COMMIT() asm volatile("cp.async.commit_group;")
#define CP_WAIT0()  asm volatile("cp.async.wait_group 0;" ::: "memory")
#define CP_WAIT1()  asm volatile("cp.async.wait_group 1;" ::: "memory")

// ================= Kernel 0: weight panel prep (k-major, hi/lo split) =================
__global__ void k0_weights(const float* __restrict__ wd,
                           const float* __restrict__ wcu,
                           const float* __restrict__ wcl)
{
    int s = blockIdx.x;                         // 0..5
    const float* w = (s < 2) ? wd : ((s < 4) ? wcu : wcl);
    int cibase = (s & 1) * 10;
    for (int i = threadIdx.x; i < 16*168; i += 256){
        int n = i / 168, k = i - n*168;
        float val = 0.0f;
        if (n < 10 && k < 160){
            int ci = k >> 4, tp = k & 15;
            if (tp < 9) val = w[(n*20 + cibase + ci)*9 + tp];
        }
        unsigned u = __float_as_uint(val);
        unsigned short hb = (unsigned short)(u >> 16);
        float lof = val - __uint_as_float(u & 0xffff0000u);
        __nv_bfloat16 lb = __float2bfloat16(lof);
        g_wp[(size_t)(2*s)*2688 + i]   = hb;
        g_wp[(size_t)(2*s+1)*2688 + i] = *(unsigned short*)&lb;
    }
}

// ================= Kernel 1: pointwise attention / maps / premult + slot0 =================
__global__ __launch_bounds__(256) void k1_pointwise(
    const float* __restrict__ f_nodes,
    const float* __restrict__ h_nodes,
    const float* __restrict__ p_nodes,
    const float* __restrict__ w_dmap, const float* __restrict__ b_dmap,
    const float* __restrict__ w_cau,  const float* __restrict__ b_cau,
    const float* __restrict__ w_cal,  const float* __restrict__ b_cal,
    float* __restrict__ out_decomp, float* __restrict__ out_cmu, float* __restrict__ out_cml,
    float* __restrict__ out_xh)
{
    __shared__ float s_wd[90], s_bd[3], s_wcau[40], s_wcal[20], s_bc[2];
    int t = threadIdx.x;
    if (t < 90)              s_wd[t]        = w_dmap[t];
    if (t >= 96 && t < 99)   s_bd[t-96]     = b_dmap[t-96];
    if (t >= 128 && t < 168) s_wcau[t-128]  = w_cau[t-128];
    if (t >= 192 && t < 212) s_wcal[t-192]  = w_cal[t-192];
    if (t == 224) s_bc[0] = b_cau[0];
    if (t == 225) s_bc[1] = b_cal[0];
    __syncthreads();

    int pix = (blockIdx.x*256 + t)*4;
    int b = pix / HW, p = pix - b*HW;

    const float* f1b = f_nodes + (size_t)(1*NB + b)*CHW + p;
    const float* h1b = h_nodes + (size_t)(1*NB + b)*CHW + p;
    const float* h2b = h_nodes + (size_t)(2*NB + b)*CHW + p;

    float4 f[10];
    float4 dm0 = f4s(s_bd[0]), dm1 = f4s(s_bd[1]), dm2 = f4s(s_bd[2]);
    #pragma unroll
    for (int c=0;c<10;c++){
        f[c]       = *(const float4*)(f1b + c*HW);
        float4 u1  = *(const float4*)(h1b + c*HW);
        float4 u2  = *(const float4*)(h2b + c*HW);
        dm0 = f4fma(s_wd[ 0+c],f[c],dm0); dm0 = f4fma(s_wd[10+c],u1,dm0); dm0 = f4fma(s_wd[20+c],u2,dm0);
        dm1 = f4fma(s_wd[30+c],f[c],dm1); dm1 = f4fma(s_wd[40+c],u1,dm1); dm1 = f4fma(s_wd[50+c],u2,dm1);
        dm2 = f4fma(s_wd[60+c],f[c],dm2); dm2 = f4fma(s_wd[70+c],u1,dm2); dm2 = f4fma(s_wd[80+c],u2,dm2);
    }

    float4 att1, att2;
    {
        float d0v[4] = {dm0.x,dm0.y,dm0.z,dm0.w};
        float d1v[4] = {dm1.x,dm1.y,dm1.z,dm1.w};
        float d2v[4] = {dm2.x,dm2.y,dm2.z,dm2.w};
        float a1v[4], a2v[4];
        #pragma unroll
        for (int i=0;i<4;i++){
            float mx = fmaxf(d0v[i], fmaxf(d1v[i], d2v[i]));
            float e0 = expf(d0v[i]-mx), e1 = expf(d1v[i]-mx), e2 = expf(d2v[i]-mx);
            float inv = 1.0f/(e0+e1+e2);
            a1v[i] = e1*inv; a2v[i] = e2*inv;
        }
        att1 = make_float4(a1v[0],a1v[1],a1v[2],a1v[3]);
        att2 = make_float4(a2v[0],a2v[1],a2v[2],a2v[3]);
    }

    float* a1p = g_a1 + (size_t)b*CHW + p;
    float* a2p = g_a2 + (size_t)b*CHW + p;
    #pragma unroll
    for (int c=0;c<10;c++){
        *(float4*)(a1p + c*HW) = make_float4(f[c].x*att1.x, f[c].y*att1.y, f[c].z*att1.z, f[c].w*att1.w);
        *(float4*)(a2p + c*HW) = make_float4(f[c].x*att2.x, f[c].y*att2.y, f[c].z*att2.z, f[c].w*att2.w);
    }

    *(float4*)(out_decomp + (size_t)(b*3+0)*HW + p) = dm0;
    *(float4*)(out_decomp + (size_t)(b*3+1)*HW + p) = dm1;
    *(float4*)(out_decomp + (size_t)(b*3+2)*HW + p) = dm2;

    float4 su = f4s(s_bc[0]);
    #pragma unroll
    for (int j=0;j<4;j++){
        const float* pp = p_nodes + (size_t)((j+1)*NB + b)*CHW + p;
        #pragma unroll
        for (int c=0;c<10;c++) su = f4fma(s_wcau[j*10+c], *(const float4*)(pp + c*HW), su);
    }
    float4 mu = make_float4(sigmoidf_(su.x), sigmoidf_(su.y), sigmoidf_(su.z), sigmoidf_(su.w));
    *(float4*)(out_cmu + (size_t)b*HW + p) = mu;

    float4 sl = f4s(s_bc[1]);
    #pragma unroll
    for (int j=0;j<2;j++){
        const float* pp = p_nodes + (size_t)((j+5)*NB + b)*CHW + p;
        #pragma unroll
        for (int c=0;c<10;c++) sl = f4fma(s_wcal[j*10+c], *(const float4*)(pp + c*HW), sl);
    }
    float4 ml = make_float4(sigmoidf_(sl.x), sigmoidf_(sl.y), sigmoidf_(sl.z), sigmoidf_(sl.w));
    *(float4*)(out_cml + (size_t)b*HW + p) = ml;

    #pragma unroll
    for (int j=0;j<4;j++){
        const float* pp = p_nodes + (size_t)((j+1)*NB + b)*CHW + p;
        float* od = g_pm + (size_t)(j*NB + b)*CHW + p;
        #pragma unroll
        for (int c=0;c<10;c++){
            float4 v = *(const float4*)(pp + c*HW);
            *(float4*)(od + c*HW) = make_float4(v.x*mu.x, v.y*mu.y, v.z*mu.z, v.w*mu.w);
        }
    }
    #pragma unroll
    for (int j=0;j<2;j++){
        const float* pp = p_nodes + (size_t)((j+5)*NB + b)*CHW + p;
        float* od = g_pm + (size_t)((4+j)*NB + b)*CHW + p;
        #pragma unroll
        for (int c=0;c<10;c++){
            float4 v = *(const float4*)(pp + c*HW);
            *(float4*)(od + c*HW) = make_float4(v.x*ml.x, v.y*ml.y, v.z*ml.z, v.w*ml.w);
        }
    }

    const float* h0 = h_nodes + (size_t)b*CHW + p;
    float* o0 = out_xh + (size_t)b*CHW + p;
    #pragma unroll
    for (int c=0;c<10;c++) *(float4*)(o0 + c*HW) = *(const float4*)(h0 + c*HW);
}

// ================= Kernel 2 helpers =================
__device__ __forceinline__ void stage_tile(char* smembase, int toff, const float* __restrict__ src,
                                           int tid, int x0, int y0)
{
    unsigned sbase = smem_to_u32(smembase + toff);
    #pragma unroll
    for (int j=0;j<5;j++){
        int i = tid + j*128;
        if (i < TILE_CHUNKS){
            int ci = i/60, rem = i - ci*60;
            int r = rem/10, c4 = rem - r*10;
            int gy = y0-1+r, gx = x0-4+c4*4;
            bool in = (gy>=0) & (gy<NH) & (gx>=0) & (gx<NW);
            const float* g = src + (size_t)ci*HW + (in ? (gy*NW+gx) : 0);
            unsigned d = sbase + (unsigned)((ci*TCI_STRIDE + r*TROWP + c4*4)*4);
            int ssz = in ? 16 : 0;
            asm volatile("cp.async.cg.shared.global [%0], [%1], 16, %2;" :: "r"(d), "l"(g), "r"(ssz));
        }
    }
}

// Dekker split: hi = truncate-to-bf16 pair, lo = exact residual rounded to bf16 pair
__device__ __forceinline__ void pack_hilo(float f0, float f1, uint32_t &hi, uint32_t &lo){
    uint32_t u0 = __float_as_uint(f0), u1 = __float_as_uint(f1);
    asm("prmt.b32 %0, %1, %2, 0x7632;" : "=r"(hi) : "r"(u0), "r"(u1));
    float l0 = f0 - __uint_as_float(u0 & 0xffff0000u);
    float l1 = f1 - __uint_as_float(u1 & 0xffff0000u);
    asm("cvt.rn.bf16x2.f32 %0, %1, %2;" : "=r"(lo) : "f"(l1), "f"(l0));
}

#define MMA_BF16(c, a0,a1,a2,a3, b0,b1) \
    asm volatile("mma.sync.aligned.m16n8k16.row.col.f32.bf16.bf16.f32 " \
        "{%0,%1,%2,%3}, {%4,%5,%6,%7}, {%8,%9}, {%0,%1,%2,%3};" \
        : "+f"((c)[0]), "+f"((c)[1]), "+f"((c)[2]), "+f"((c)[3]) \
        : "r"(a0), "r"(a1), "r"(a2), "r"(a3), "r"(b0), "r"(b1))

// one conv (implicit GEMM, split bf16 x3 terms) accumulated into C[s][n][4]
__device__ __forceinline__ void conv_hmma(
    float C[2][2][4], const float* tile,
    const uint32_t* ph, const uint32_t* pl,
    int w, int g, int t, int off0, int off1)
{
    #pragma unroll 1
    for (int ci=0; ci<10; ci++){
        uint32_t bh0[2], bh1[2], bl0[2], bl1[2];
        #pragma unroll
        for (int n=0;n<2;n++){
            int bi = (n*8+g)*KPW + ci*8 + t;
            bh0[n]=ph[bi]; bh1[n]=ph[bi+4];
            bl0[n]=pl[bi]; bl1[n]=pl[bi+4];
        }
        const float* f = tile + ci*TCI_STRIDE + w*TROWP + g + 3;
        #pragma unroll
        for (int s=0;s<2;s++){
            const float* fs = f + 16*s;
            float v0 = fs[off0],   v1 = fs[off1];
            float w0 = fs[off0+8], w1 = fs[off1+8];
            uint32_t ah0, al0, ah1, al1, ah2, al2, ah3, al3;
            pack_hilo(v0, v1, ah0, al0);
            pack_hilo(w0, w1, ah1, al1);
            float v8 = fs[82], w8 = fs[90];   // tap 8 (dy2,dx2); valid only for t==0
            pack_hilo(v8, 0.0f, ah2, al2);
            pack_hilo(w8, 0.0f, ah3, al3);
            if (t != 0){ ah2=0u; al2=0u; ah3=0u; al3=0u; }
            #pragma unroll
            for (int n=0;n<2;n++){
                MMA_BF16(C[s][n], ah0,ah1,ah2,ah3, bh0[n], bh1[n]);  // hi*hi
                MMA_BF16(C[s][n], al0,al1,al2,al3, bh0[n], bh1[n]);  // lo*hi
                MMA_BF16(C[s][n], ah0,ah1,ah2,ah3, bl0[n], bl1[n]);  // hi*lo
            }
        }
    }
}

// ================= Kernel 2: HMMA fused convs + GRU =================
__global__ __launch_bounds__(128,2) void k2_conv(
    const float* __restrict__ h_nodes,
    const float* __restrict__ g_decomp, const float* __restrict__ be_decomp,
    const float* __restrict__ g_cu, const float* __restrict__ be_cu,
    const float* __restrict__ g_cl, const float* __restrict__ be_cl,
    const float* __restrict__ wg_u, const float* __restrict__ bg_u,
    const float* __restrict__ wc_u, const float* __restrict__ g_u, const float* __restrict__ be_u,
    const float* __restrict__ wg_l, const float* __restrict__ bg_l,
    const float* __restrict__ wc_l, const float* __restrict__ g_l, const float* __restrict__ be_l,
    float* __restrict__ out_xh)
{
    extern __shared__ __align__(16) char smem[];
    float* s_par = (float*)(smem + SM_PAR);
    float* s_msg = (float*)(smem + SM_MSG);

    int z = blockIdx.z; int b = z >> 1; int half = z & 1;
    const float* gcv  = half ? g_cl  : g_cu;
    const float* becv = half ? be_cl : be_cu;
    const float* aX   = (half ? g_a2 : g_a1) + (size_t)b*CHW;
    const float* hX   = h_nodes + (size_t)((half?2:1)*NB + b)*CHW;
    const float* wgv  = half ? wg_l : wg_u;
    const float* bgv  = half ? bg_l : bg_u;
    const float* wcv  = half ? wc_l : wc_u;
    const float* ggv  = half ? g_l  : g_u;
    const float* bev  = half ? be_l : be_u;
    float* outp       = out_xh + (size_t)((half?2:1)*NB + b)*CHW;
    int nparts = half ? 2 : 4;
    int pidx0  = half ? 4 : 0;

    int tid = threadIdx.x;
    int w = tid >> 5, lane = tid & 31;
    int g = lane >> 2, t = lane & 3;
    int x0 = blockIdx.x*TILE_W, y0 = blockIdx.y*TILE_H;

    // per-thread tap offsets: taps 2t, 2t+1 -> (dy,dx) -> dy*40+dx
    int tp0 = 2*t, tp1 = 2*t+1;
    int dy0 = tp0/3, dx0 = tp0 - 3*dy0;
    int dy1 = tp1/3, dx1 = tp1 - 3*dy1;
    int off0 = dy0*TROWP + dx0, off1 = dy1*TROWP + dx1;

    // ---- issue panel + a/h tile cp.async (one group) ----
    {
        unsigned sb = smem_to_u32(smem);
        #pragma unroll
        for (int j=0;j<21;j++){
            int i = tid + j*128;   // 2688 16B chunks = 43008 B
            int lp = i / 336, within = i - lp*336;
            int gp = (lp < 4) ? lp : ((half ? 8 : 4) + (lp-4));
            const char* gsrc = (const char*)g_wp + (size_t)gp*PANEL_B + within*16;
            unsigned d = sb + (unsigned)(SM_PANELS + lp*PANEL_B + within*16);
            asm volatile("cp.async.cg.shared.global [%0], [%1], 16;" :: "r"(d), "l"(gsrc));
        }
        stage_tile(smem, SM_T0, aX, tid, x0, y0);
        stage_tile(smem, SM_T1, hX, tid, x0, y0);
        CP_COMMIT();
    }

    // ---- params ----
    if (tid < 10){
        s_par[P_GD+tid]=g_decomp[tid]; s_par[P_BED+tid]=be_decomp[tid];
        s_par[P_GC+tid]=gcv[tid];      s_par[P_BEC+tid]=becv[tid];
        s_par[P_GG+tid]=ggv[tid];      s_par[P_BEG+tid]=bev[tid];
    }
    if (tid >= 32 && tid < 72) s_par[P_WG + tid-32] = wgv[tid-32];
    if (tid == 72) { s_par[P_BG]=bgv[0]; s_par[P_BG+1]=bgv[1]; }
    if (tid < 100){ s_par[P_WC+tid] = wcv[tid]; s_par[P_WC+100+tid] = wcv[100+tid]; }

    CP_WAIT0();
    __syncthreads();            // panels + a + h visible

    // issue part0 -> T2
    stage_tile(smem, SM_T2, g_pm + (size_t)(pidx0*NB + b)*CHW, tid, x0, y0);
    CP_COMMIT();

    const uint32_t* pan = (const uint32_t*)(smem + SM_PANELS);
    const uint32_t* p_wdta_h = pan + 0*(PANEL_B/4);
    const uint32_t* p_wdta_l = pan + 1*(PANEL_B/4);
    const uint32_t* p_wdth_h = pan + 2*(PANEL_B/4);
    const uint32_t* p_wdth_l = pan + 3*(PANEL_B/4);
    const uint32_t* p_wcth_h = pan + 4*(PANEL_B/4);
    const uint32_t* p_wcth_l = pan + 5*(PANEL_B/4);
    const uint32_t* p_wctp_h = pan + 6*(PANEL_B/4);
    const uint32_t* p_wctp_l = pan + 7*(PANEL_B/4);

    // per-thread BN constants (channels 2t,2t+1, 8+2t, 9+2t)
    int o0 = 2*t, o1 = 2*t+1, o8 = 8+2*t, o9 = 9+2*t;
    float gd_[4]  = { s_par[P_GD+o0],  s_par[P_GD+o1],  s_par[P_GD+o8],  s_par[P_GD+o9]  };
    float bed_[4] = { s_par[P_BED+o0], s_par[P_BED+o1], s_par[P_BED+o8], s_par[P_BED+o9] };
    float gc_[4]  = { s_par[P_GC+o0],  s_par[P_GC+o1],  s_par[P_GC+o8],  s_par[P_GC+o9]  };
    float bec_[4] = { s_par[P_BEC+o0], s_par[P_BEC+o1], s_par[P_BEC+o8], s_par[P_BEC+o9] };

    // ---- decomp conv: Dd = wdt[:,0:10](x)a + wdt[:,10:20](x)h ----
    float Dd[2][2][4];
    #pragma unroll
    for (int s=0;s<2;s++)
        #pragma unroll
        for (int n=0;n<2;n++)
            #pragma unroll
            for (int j=0;j<4;j++) Dd[s][n][j] = 0.0f;
    conv_hmma(Dd, (const float*)(smem + SM_T0), p_wdta_h, p_wdta_l, w, g, t, off0, off1);
    conv_hmma(Dd, (const float*)(smem + SM_T1), p_wdth_h, p_wdth_l, w, g, t, off0, off1);

    // ---- shared A term: accA = wct[:,0:10](x)h ----
    float accA[2][2][4];
    #pragma unroll
    for (int s=0;s<2;s++)
        #pragma unroll
        for (int n=0;n<2;n++)
            #pragma unroll
            for (int j=0;j<4;j++) accA[s][n][j] = 0.0f;
    conv_hmma(accA, (const float*)(smem + SM_T1), p_wcth_h, p_wcth_l, w, g, t, off0, off1);

    // msg = relu(bn_d(Dd))  (in place)
    #pragma unroll
    for (int s=0;s<2;s++)
        #pragma unroll
        for (int n=0;n<2;n++)
            #pragma unroll
            for (int j=0;j<4;j++){
                int oi = n*2 + (j&1);
                Dd[s][n][j] = fmaxf(fmaf(gd_[oi], Dd[s][n][j], bed_[oi]), 0.0f);
            }

    __syncthreads();   // all warps done reading T0/T1 before ring reuse

    // ---- part loop (ring T2,T0,T1) ----
    const int bufoff[3] = {SM_T2, SM_T0, SM_T1};
    for (int part=0; part<nparts; part++){
        if (part+1 < nparts){
            stage_tile(smem, bufoff[(part+1)%3], g_pm + (size_t)((pidx0+part+1)*NB + b)*CHW, tid, x0, y0);
            CP_COMMIT();
            CP_WAIT1();
        } else {
            CP_WAIT0();
        }
        __syncthreads();

        float Cp[2][2][4];
        #pragma unroll
        for (int s=0;s<2;s++)
            #pragma unroll
            for (int n=0;n<2;n++)
                #pragma unroll
                for (int j=0;j<4;j++) Cp[s][n][j] = accA[s][n][j];
        conv_hmma(Cp, (const float*)(smem + bufoff[part%3]), p_wctp_h, p_wctp_l, w, g, t, off0, off1);
        #pragma unroll
        for (int s=0;s<2;s++)
            #pragma unroll
            for (int n=0;n<2;n++)
                #pragma unroll
                for (int j=0;j<4;j++){
                    int oi = n*2 + (j&1);
                    Dd[s][n][j] += fmaxf(fmaf(gc_[oi], Cp[s][n][j], bec_[oi]), 0.0f);
                }
    }

    // ---- scatter msg fragments to smem [m][out] ----
    #pragma unroll
    for (int s=0;s<2;s++){
        int m0 = w*32 + s*16 + g;
        #pragma unroll
        for (int n=0;n<2;n++){
            if (n == 0 || t == 0){
                int oc = n*8 + 2*t;
                *(float2*)&s_msg[m0*12 + oc]     = make_float2(Dd[s][n][0], Dd[s][n][1]);
                *(float2*)&s_msg[(m0+8)*12 + oc] = make_float2(Dd[s][n][2], Dd[s][n][3]);
            }
        }
    }
    __syncthreads();

    // ---------- GRU epilogue (1 px per thread) ----------
    int py = y0 + (tid >> 5), pxx = x0 + (tid & 31);
    float msg[10], hcen[10];
    #pragma unroll
    for (int c=0;c<10;c++) msg[c] = s_msg[tid*12 + c];
    {
        const float* hc = hX + (size_t)py*NW + pxx;
        #pragma unroll
        for (int c=0;c<10;c++) hcen[c] = hc[(size_t)c*HW];
    }
    float g0 = s_par[P_BG], g1 = s_par[P_BG+1];
    #pragma unroll
    for (int c=0;c<10;c++){
        g0 = fmaf(s_par[P_WG+c],    msg[c],  g0);
        g0 = fmaf(s_par[P_WG+10+c], hcen[c], g0);
        g1 = fmaf(s_par[P_WG+20+c], msg[c],  g1);
        g1 = fmaf(s_par[P_WG+30+c], hcen[c], g1);
    }
    float rr = sigmoidf_(g0), uu = sigmoidf_(g1);
    float rh[10];
    #pragma unroll
    for (int c=0;c<10;c++) rh[c] = rr*hcen[c];

    float* op = outp + (size_t)py*NW + pxx;
    #pragma unroll
    for (int o=0;o<10;o++){
        float s = 0.0f;
        #pragma unroll
        for (int c=0;c<10;c++){
            s = fmaf(s_par[P_WC + o*20 + c],      msg[c], s);
            s = fmaf(s_par[P_WC + o*20 + 10 + c], rh[c],  s);
        }
        float cn = fmaf(s_par[P_GG+o], s, s_par[P_BEG+o]);
        cn = cn > 0.0f ? cn : 0.01f*cn;
        op[(size_t)o*HW] = (1.0f-uu)*hcen[o] + uu*cn;
    }
}

// ================= launcher =================
extern "C" void kernel_launch(void* const* d_in, const int* in_sizes, int n_in,
                              void* d_out, int out_size)
{
    const float* f_nodes  = (const float*)d_in[0];
    const float* h_nodes  = (const float*)d_in[1];
    const float* p_nodes  = (const float*)d_in[2];
    const float* w_dmap   = (const float*)d_in[4];
    const float* b_dmap   = (const float*)d_in[5];
    const float* w_decomp = (const float*)d_in[6];
    const float* g_decomp = (const float*)d_in[7];
    const float* be_decomp= (const float*)d_in[8];
    const float* w_cau    = (const float*)d_in[9];
    const float* b_cau    = (const float*)d_in[10];
    const float* w_cal    = (const float*)d_in[11];
    const float* b_cal    = (const float*)d_in[12];
    const float* w_cu     = (const float*)d_in[13];
    const float* g_cu     = (const float*)d_in[14];
    const float* be_cu    = (const float*)d_in[15];
    const float* w_cl     = (const float*)d_in[16];
    const float* g_cl     = (const float*)d_in[17];
    const float* be_cl    = (const float*)d_in[18];
    const float* wg_u     = (const float*)d_in[19];
    const float* bg_u     = (const float*)d_in[20];
    const float* wc_u     = (const float*)d_in[21];
    const float* g_u      = (const float*)d_in[22];
    const float* be_u     = (const float*)d_in[23];
    const float* wg_l     = (const float*)d_in[24];
    const float* bg_l     = (const float*)d_in[25];
    const float* wc_l     = (const float*)d_in[26];
    const float* g_l      = (const float*)d_in[27];
    const float* be_l     = (const float*)d_in[28];

    float* out        = (float*)d_out;
    float* out_decomp = out + (size_t)3*NB*CHW;
    float* out_cmu    = out_decomp + (size_t)NB*3*HW;
    float* out_cml    = out_cmu + (size_t)NB*HW;

    k0_weights<<<6, 256>>>(w_decomp, w_cu, w_cl);

    k1_pointwise<<<NB*HW/1024, 256>>>(f_nodes, h_nodes, p_nodes,
                                      w_dmap, b_dmap, w_cau, b_cau, w_cal, b_cal,
                                      out_decomp, out_cmu, out_cml, out);

    static int smem_set = 0;
    if (!smem_set){
        cudaFuncSetAttribute(k2_conv, cudaFuncAttributeMaxDynamicSharedMemorySize, SMEM_BYTES);
        smem_set = 1;
    }
    dim3 g2(NW/TILE_W, NH/TILE_H, 2*NB), b2(128, 1, 1);
    k2_conv<<<g2, b2, SMEM_BYTES>>>(h_nodes,
                                    g_decomp, be_decomp,
                                    g_cu, be_cu, g_cl, be_cl,
                                    wg_u, bg_u, wc_u, g_u, be_u,
                                    wg_l, bg_l, wc_l, g_l, be_l,
                                    out);
}

// round 12
// speedup vs baseline: 1.1636x; 1.1636x over previous
#include <cuda_runtime.h>
#include <cuda_bf16.h>
#include <cstdint>

#define NB 8
#define NC 10
#define NH 192
#define NW 192
#define HW (NH*NW)
#define CHW (NC*HW)

// ---------------- k2 geometry ----------------
#define TILE_W 32
#define TILE_H 8
#define TROWP 40              /* tile row floats, base gx = x0-4 */
#define TROWS 10              /* 8 + 2 halo */
#define TCI_STRIDE 400        /* TROWS * TROWP */
#define TILE_B 16000          /* 10ch * 400 * 4 bytes */
#define TILE_CHUNKS 1000      /* float4 chunks per 10-ch tile */

// weight panels: [16 outs x 168 K-halves] bf16, row stride 84 words
#define KPW 84
#define PANEL_B 5376          /* 16*168*2 bytes */

// smem byte layout
#define SM_PANELS 0           /* 8 local panels = 43008 */
#define SM_T0 43008
#define SM_T1 (SM_T0 + TILE_B)
#define SM_T2 (SM_T1 + TILE_B)
#define SM_PAR (SM_T2 + TILE_B)   /* 91008 */
#define SMEM_BYTES (SM_PAR + 1216)

// param offsets (floats)
#define P_GD 0
#define P_BED 10
#define P_GC 20
#define P_BEC 30
#define P_GG 40
#define P_BEG 50
#define P_WG 60
#define P_BG 100
#define P_WC 102

// ---------------- scratch (static device globals; no allocation) ----------------
__device__ __align__(16) float g_a1[NB*CHW];
__device__ __align__(16) float g_a2[NB*CHW];
__device__ __align__(16) float g_pm[6*NB*CHW];
// 12 global panels: s=0..5 {wdt0,wdt1,wcu0,wcu1,wcl0,wcl1} x {hi,lo}
__device__ __align__(16) unsigned short g_wp[12*16*168];

__device__ __forceinline__ float sigmoidf_(float x){ return 1.0f/(1.0f+expf(-x)); }
__device__ __forceinline__ float4 f4fma(float s, float4 v, float4 a){
    return make_float4(fmaf(s,v.x,a.x), fmaf(s,v.y,a.y), fmaf(s,v.z,a.z), fmaf(s,v.w,a.w));
}
__device__ __forceinline__ float4 f4s(float s){ return make_float4(s,s,s,s); }

__device__ __forceinline__ uint32_t smem_to_u32(const void* p) {
    uint32_t a;
    asm("{ .reg .u64 t; cvta.to.shared.u64 t, %1; cvt.u32.u64 %0, t; }" : "=r"(a) : "l"(p));
    return a;
}
#define CP_COMMIT() asm volatile("cp.async.commit_group;")
#define CP_WAIT0()  asm volatile("cp.async.wait_group 0;" ::: "memory")
#define CP_WAIT1()  asm volatile("cp.async.wait_group 1;" ::: "memory")

// ================= Kernel 0: weight panel prep (k-major, hi/lo split) =================
__global__ void k0_weights(const float* __restrict__ wd,
                           const float* __restrict__ wcu,
                           const float* __restrict__ wcl)
{
    int s = blockIdx.x;                         // 0..5
    const float* w = (s < 2) ? wd : ((s < 4) ? wcu : wcl);
    int cibase = (s & 1) * 10;
    for (int i = threadIdx.x; i < 16*168; i += 256){
        int n = i / 168, k = i - n*168;
        float val = 0.0f;
        if (n < 10 && k < 160){
            int ci = k >> 4, tp = k & 15;
            if (tp < 9) val = w[(n*20 + cibase + ci)*9 + tp];
        }
        unsigned u = __float_as_uint(val);
        unsigned short hb = (unsigned short)(u >> 16);
        float lof = val - __uint_as_float(u & 0xffff0000u);
        __nv_bfloat16 lb = __float2bfloat16(lof);
        g_wp[(size_t)(2*s)*2688 + i]   = hb;
        g_wp[(size_t)(2*s+1)*2688 + i] = *(unsigned short*)&lb;
    }
}

// ================= Kernel 1: pointwise attention / maps / premult + slot0 =================
__global__ __launch_bounds__(256) void k1_pointwise(
    const float* __restrict__ f_nodes,
    const float* __restrict__ h_nodes,
    const float* __restrict__ p_nodes,
    const float* __restrict__ w_dmap, const float* __restrict__ b_dmap,
    const float* __restrict__ w_cau,  const float* __restrict__ b_cau,
    const float* __restrict__ w_cal,  const float* __restrict__ b_cal,
    float* __restrict__ out_decomp, float* __restrict__ out_cmu, float* __restrict__ out_cml,
    float* __restrict__ out_xh)
{
    __shared__ float s_wd[90], s_bd[3], s_wcau[40], s_wcal[20], s_bc[2];
    int t = threadIdx.x;
    if (t < 90)              s_wd[t]        = w_dmap[t];
    if (t >= 96 && t < 99)   s_bd[t-96]     = b_dmap[t-96];
    if (t >= 128 && t < 168) s_wcau[t-128]  = w_cau[t-128];
    if (t >= 192 && t < 212) s_wcal[t-192]  = w_cal[t-192];
    if (t == 224) s_bc[0] = b_cau[0];
    if (t == 225) s_bc[1] = b_cal[0];
    __syncthreads();

    int pix = (blockIdx.x*256 + t)*4;
    int b = pix / HW, p = pix - b*HW;

    const float* f1b = f_nodes + (size_t)(1*NB + b)*CHW + p;
    const float* h1b = h_nodes + (size_t)(1*NB + b)*CHW + p;
    const float* h2b = h_nodes + (size_t)(2*NB + b)*CHW + p;

    float4 f[10];
    float4 dm0 = f4s(s_bd[0]), dm1 = f4s(s_bd[1]), dm2 = f4s(s_bd[2]);
    #pragma unroll
    for (int c=0;c<10;c++){
        f[c]       = *(const float4*)(f1b + c*HW);
        float4 u1  = *(const float4*)(h1b + c*HW);
        float4 u2  = *(const float4*)(h2b + c*HW);
        dm0 = f4fma(s_wd[ 0+c],f[c],dm0); dm0 = f4fma(s_wd[10+c],u1,dm0); dm0 = f4fma(s_wd[20+c],u2,dm0);
        dm1 = f4fma(s_wd[30+c],f[c],dm1); dm1 = f4fma(s_wd[40+c],u1,dm1); dm1 = f4fma(s_wd[50+c],u2,dm1);
        dm2 = f4fma(s_wd[60+c],f[c],dm2); dm2 = f4fma(s_wd[70+c],u1,dm2); dm2 = f4fma(s_wd[80+c],u2,dm2);
    }

    float4 att1, att2;
    {
        float d0v[4] = {dm0.x,dm0.y,dm0.z,dm0.w};
        float d1v[4] = {dm1.x,dm1.y,dm1.z,dm1.w};
        float d2v[4] = {dm2.x,dm2.y,dm2.z,dm2.w};
        float a1v[4], a2v[4];
        #pragma unroll
        for (int i=0;i<4;i++){
            float mx = fmaxf(d0v[i], fmaxf(d1v[i], d2v[i]));
            float e0 = expf(d0v[i]-mx), e1 = expf(d1v[i]-mx), e2 = expf(d2v[i]-mx);
            float inv = 1.0f/(e0+e1+e2);
            a1v[i] = e1*inv; a2v[i] = e2*inv;
        }
        att1 = make_float4(a1v[0],a1v[1],a1v[2],a1v[3]);
        att2 = make_float4(a2v[0],a2v[1],a2v[2],a2v[3]);
    }

    float* a1p = g_a1 + (size_t)b*CHW + p;
    float* a2p = g_a2 + (size_t)b*CHW + p;
    #pragma unroll
    for (int c=0;c<10;c++){
        *(float4*)(a1p + c*HW) = make_float4(f[c].x*att1.x, f[c].y*att1.y, f[c].z*att1.z, f[c].w*att1.w);
        *(float4*)(a2p + c*HW) = make_float4(f[c].x*att2.x, f[c].y*att2.y, f[c].z*att2.z, f[c].w*att2.w);
    }

    *(float4*)(out_decomp + (size_t)(b*3+0)*HW + p) = dm0;
    *(float4*)(out_decomp + (size_t)(b*3+1)*HW + p) = dm1;
    *(float4*)(out_decomp + (size_t)(b*3+2)*HW + p) = dm2;

    float4 su = f4s(s_bc[0]);
    #pragma unroll
    for (int j=0;j<4;j++){
        const float* pp = p_nodes + (size_t)((j+1)*NB + b)*CHW + p;
        #pragma unroll
        for (int c=0;c<10;c++) su = f4fma(s_wcau[j*10+c], *(const float4*)(pp + c*HW), su);
    }
    float4 mu = make_float4(sigmoidf_(su.x), sigmoidf_(su.y), sigmoidf_(su.z), sigmoidf_(su.w));
    *(float4*)(out_cmu + (size_t)b*HW + p) = mu;

    float4 sl = f4s(s_bc[1]);
    #pragma unroll
    for (int j=0;j<2;j++){
        const float* pp = p_nodes + (size_t)((j+5)*NB + b)*CHW + p;
        #pragma unroll
        for (int c=0;c<10;c++) sl = f4fma(s_wcal[j*10+c], *(const float4*)(pp + c*HW), sl);
    }
    float4 ml = make_float4(sigmoidf_(sl.x), sigmoidf_(sl.y), sigmoidf_(sl.z), sigmoidf_(sl.w));
    *(float4*)(out_cml + (size_t)b*HW + p) = ml;

    #pragma unroll
    for (int j=0;j<4;j++){
        const float* pp = p_nodes + (size_t)((j+1)*NB + b)*CHW + p;
        float* od = g_pm + (size_t)(j*NB + b)*CHW + p;
        #pragma unroll
        for (int c=0;c<10;c++){
            float4 v = *(const float4*)(pp + c*HW);
            *(float4*)(od + c*HW) = make_float4(v.x*mu.x, v.y*mu.y, v.z*mu.z, v.w*mu.w);
        }
    }
    #pragma unroll
    for (int j=0;j<2;j++){
        const float* pp = p_nodes + (size_t)((j+5)*NB + b)*CHW + p;
        float* od = g_pm + (size_t)((4+j)*NB + b)*CHW + p;
        #pragma unroll
        for (int c=0;c<10;c++){
            float4 v = *(const float4*)(pp + c*HW);
            *(float4*)(od + c*HW) = make_float4(v.x*ml.x, v.y*ml.y, v.z*ml.z, v.w*ml.w);
        }
    }

    const float* h0 = h_nodes + (size_t)b*CHW + p;
    float* o0 = out_xh + (size_t)b*CHW + p;
    #pragma unroll
    for (int c=0;c<10;c++) *(float4*)(o0 + c*HW) = *(const float4*)(h0 + c*HW);
}

// ================= Kernel 2 helpers =================
__device__ __forceinline__ void stage_tile(char* smembase, int toff, const float* __restrict__ src,
                                           int tid, int x0, int y0)
{
    unsigned sbase = smem_to_u32(smembase + toff);
    #pragma unroll
    for (int j=0;j<4;j++){
        int i = tid + j*256;
        if (i < TILE_CHUNKS){
            int ci = i/100, rem = i - ci*100;
            int r = rem/10, c4 = rem - r*10;
            int gy = y0-1+r, gx = x0-4+c4*4;
            bool in = (gy>=0) & (gy<NH) & (gx>=0) & (gx<NW);
            const float* g = src + (size_t)ci*HW + (in ? (gy*NW+gx) : 0);
            unsigned d = sbase + (unsigned)((ci*TCI_STRIDE + r*TROWP + c4*4)*4);
            int ssz = in ? 16 : 0;
            asm volatile("cp.async.cg.shared.global [%0], [%1], 16, %2;" :: "r"(d), "l"(g), "r"(ssz));
        }
    }
}

// Dekker split: hi = truncate-to-bf16 pair, lo = exact residual rounded to bf16 pair
__device__ __forceinline__ void pack_hilo(float f0, float f1, uint32_t &hi, uint32_t &lo){
    uint32_t u0 = __float_as_uint(f0), u1 = __float_as_uint(f1);
    asm("prmt.b32 %0, %1, %2, 0x7632;" : "=r"(hi) : "r"(u0), "r"(u1));
    float l0 = f0 - __uint_as_float(u0 & 0xffff0000u);
    float l1 = f1 - __uint_as_float(u1 & 0xffff0000u);
    asm("cvt.rn.bf16x2.f32 %0, %1, %2;" : "=r"(lo) : "f"(l1), "f"(l0));
}

#define MMA_BF16(c, a0,a1,a2,a3, b0,b1) \
    asm volatile("mma.sync.aligned.m16n8k16.row.col.f32.bf16.bf16.f32 " \
        "{%0,%1,%2,%3}, {%4,%5,%6,%7}, {%8,%9}, {%0,%1,%2,%3};" \
        : "+f"((c)[0]), "+f"((c)[1]), "+f"((c)[2]), "+f"((c)[3]) \
        : "r"(a0), "r"(a1), "r"(a2), "r"(a3), "r"(b0), "r"(b1))

// one conv (implicit GEMM, split bf16 x3 terms) accumulated into C[s][n][4]
__device__ __forceinline__ void conv_hmma(
    float C[2][2][4], const float* tile,
    const uint32_t* ph, const uint32_t* pl,
    int w, int g, int t, int off0, int off1)
{
    #pragma unroll 1
    for (int ci=0; ci<10; ci++){
        uint32_t bh0[2], bh1[2], bl0[2], bl1[2];
        #pragma unroll
        for (int n=0;n<2;n++){
            int bi = (n*8+g)*KPW + ci*8 + t;
            bh0[n]=ph[bi]; bh1[n]=ph[bi+4];
            bl0[n]=pl[bi]; bl1[n]=pl[bi+4];
        }
        const float* f = tile + ci*TCI_STRIDE + w*TROWP + g + 3;
        #pragma unroll
        for (int s=0;s<2;s++){
            const float* fs = f + 16*s;
            float v0 = fs[off0],   v1 = fs[off1];
            float w0 = fs[off0+8], w1 = fs[off1+8];
            uint32_t ah0, al0, ah1, al1, ah2, al2, ah3, al3;
            pack_hilo(v0, v1, ah0, al0);
            pack_hilo(w0, w1, ah1, al1);
            float v8 = fs[82], w8 = fs[90];   // tap 8 (dy2,dx2); valid only for t==0
            pack_hilo(v8, 0.0f, ah2, al2);
            pack_hilo(w8, 0.0f, ah3, al3);
            if (t != 0){ ah2=0u; al2=0u; ah3=0u; al3=0u; }
            #pragma unroll
            for (int n=0;n<2;n++){
                MMA_BF16(C[s][n], ah0,ah1,ah2,ah3, bh0[n], bh1[n]);  // hi*hi
                MMA_BF16(C[s][n], al0,al1,al2,al3, bh0[n], bh1[n]);  // lo*hi
                MMA_BF16(C[s][n], ah0,ah1,ah2,ah3, bl0[n], bl1[n]);  // hi*lo
            }
        }
    }
}

// dual: same A fragments feed two accumulator/panel sets (h tile shared)
__device__ __forceinline__ void conv_hmma_dual(
    float C1[2][2][4], float C2[2][2][4], const float* tile,
    const uint32_t* p1h, const uint32_t* p1l,
    const uint32_t* p2h, const uint32_t* p2l,
    int w, int g, int t, int off0, int off1)
{
    #pragma unroll 1
    for (int ci=0; ci<10; ci++){
        uint32_t b1h0[2], b1h1[2], b1l0[2], b1l1[2];
        uint32_t b2h0[2], b2h1[2], b2l0[2], b2l1[2];
        #pragma unroll
        for (int n=0;n<2;n++){
            int bi = (n*8+g)*KPW + ci*8 + t;
            b1h0[n]=p1h[bi]; b1h1[n]=p1h[bi+4];
            b1l0[n]=p1l[bi]; b1l1[n]=p1l[bi+4];
            b2h0[n]=p2h[bi]; b2h1[n]=p2h[bi+4];
            b2l0[n]=p2l[bi]; b2l1[n]=p2l[bi+4];
        }
        const float* f = tile + ci*TCI_STRIDE + w*TROWP + g + 3;
        #pragma unroll
        for (int s=0;s<2;s++){
            const float* fs = f + 16*s;
            float v0 = fs[off0],   v1 = fs[off1];
            float w0 = fs[off0+8], w1 = fs[off1+8];
            uint32_t ah0, al0, ah1, al1, ah2, al2, ah3, al3;
            pack_hilo(v0, v1, ah0, al0);
            pack_hilo(w0, w1, ah1, al1);
            float v8 = fs[82], w8 = fs[90];
            pack_hilo(v8, 0.0f, ah2, al2);
            pack_hilo(w8, 0.0f, ah3, al3);
            if (t != 0){ ah2=0u; al2=0u; ah3=0u; al3=0u; }
            #pragma unroll
            for (int n=0;n<2;n++){
                MMA_BF16(C1[s][n], ah0,ah1,ah2,ah3, b1h0[n], b1h1[n]);
                MMA_BF16(C1[s][n], al0,al1,al2,al3, b1h0[n], b1h1[n]);
                MMA_BF16(C1[s][n], ah0,ah1,ah2,ah3, b1l0[n], b1l1[n]);
                MMA_BF16(C2[s][n], ah0,ah1,ah2,ah3, b2h0[n], b2h1[n]);
                MMA_BF16(C2[s][n], al0,al1,al2,al3, b2h0[n], b2h1[n]);
                MMA_BF16(C2[s][n], ah0,ah1,ah2,ah3, b2l0[n], b2l1[n]);
            }
        }
    }
}

// ================= Kernel 2: HMMA fused convs + GRU =================
__global__ __launch_bounds__(256,2) void k2_conv(
    const float* __restrict__ h_nodes,
    const float* __restrict__ g_decomp, const float* __restrict__ be_decomp,
    const float* __restrict__ g_cu, const float* __restrict__ be_cu,
    const float* __restrict__ g_cl, const float* __restrict__ be_cl,
    const float* __restrict__ wg_u, const float* __restrict__ bg_u,
    const float* __restrict__ wc_u, const float* __restrict__ g_u, const float* __restrict__ be_u,
    const float* __restrict__ wg_l, const float* __restrict__ bg_l,
    const float* __restrict__ wc_l, const float* __restrict__ g_l, const float* __restrict__ be_l,
    float* __restrict__ out_xh)
{
    extern __shared__ __align__(16) char smem[];
    float* s_par = (float*)(smem + SM_PAR);

    int z = blockIdx.z; int b = z >> 1; int half = z & 1;
    const float* gcv  = half ? g_cl  : g_cu;
    const float* becv = half ? be_cl : be_cu;
    const float* aX   = (half ? g_a2 : g_a1) + (size_t)b*CHW;
    const float* hX   = h_nodes + (size_t)((half?2:1)*NB + b)*CHW;
    const float* wgv  = half ? wg_l : wg_u;
    const float* bgv  = half ? bg_l : bg_u;
    const float* wcv  = half ? wc_l : wc_u;
    const float* ggv  = half ? g_l  : g_u;
    const float* bev  = half ? be_l : be_u;
    float* outp       = out_xh + (size_t)((half?2:1)*NB + b)*CHW;
    int nparts = half ? 2 : 4;
    int pidx0  = half ? 4 : 0;

    int tid = threadIdx.x;
    int w = tid >> 5, lane = tid & 31;
    int g = lane >> 2, t = lane & 3;
    int x0 = blockIdx.x*TILE_W, y0 = blockIdx.y*TILE_H;

    // per-thread tap offsets: taps 2t, 2t+1 -> (dy,dx) -> dy*40+dx
    int tp0 = 2*t, tp1 = 2*t+1;
    int dy0 = tp0/3, dx0 = tp0 - 3*dy0;
    int dy1 = tp1/3, dx1 = tp1 - 3*dy1;
    int off0 = dy0*TROWP + dx0, off1 = dy1*TROWP + dx1;

    // ---- issue panel + a/h tile cp.async (one group) ----
    {
        unsigned sb = smem_to_u32(smem);
        #pragma unroll
        for (int j=0;j<11;j++){
            int i = tid + j*256;   // 2688 16B chunks = 43008 B
            if (i < 2688){
                int lp = i / 336, within = i - lp*336;
                int gp = (lp < 4) ? lp : ((half ? 8 : 4) + (lp-4));
                const char* gsrc = (const char*)g_wp + (size_t)gp*PANEL_B + within*16;
                unsigned d = sb + (unsigned)(SM_PANELS + lp*PANEL_B + within*16);
                asm volatile("cp.async.cg.shared.global [%0], [%1], 16;" :: "r"(d), "l"(gsrc));
            }
        }
        stage_tile(smem, SM_T0, aX, tid, x0, y0);
        stage_tile(smem, SM_T1, hX, tid, x0, y0);
        CP_COMMIT();
    }

    // ---- params ----
    if (tid < 10){
        s_par[P_GD+tid]=g_decomp[tid]; s_par[P_BED+tid]=be_decomp[tid];
        s_par[P_GC+tid]=gcv[tid];      s_par[P_BEC+tid]=becv[tid];
        s_par[P_GG+tid]=ggv[tid];      s_par[P_BEG+tid]=bev[tid];
    }
    if (tid >= 32 && tid < 72) s_par[P_WG + tid-32] = wgv[tid-32];
    if (tid == 72) { s_par[P_BG]=bgv[0]; s_par[P_BG+1]=bgv[1]; }
    if (tid < 100){ s_par[P_WC+tid] = wcv[tid]; s_par[P_WC+100+tid] = wcv[100+tid]; }

    CP_WAIT0();
    __syncthreads();            // panels + a + h visible

    // issue part0 -> T2
    stage_tile(smem, SM_T2, g_pm + (size_t)(pidx0*NB + b)*CHW, tid, x0, y0);
    CP_COMMIT();

    const uint32_t* pan = (const uint32_t*)(smem + SM_PANELS);
    const uint32_t* p_wdta_h = pan + 0*(PANEL_B/4);
    const uint32_t* p_wdta_l = pan + 1*(PANEL_B/4);
    const uint32_t* p_wdth_h = pan + 2*(PANEL_B/4);
    const uint32_t* p_wdth_l = pan + 3*(PANEL_B/4);
    const uint32_t* p_wcth_h = pan + 4*(PANEL_B/4);
    const uint32_t* p_wcth_l = pan + 5*(PANEL_B/4);
    const uint32_t* p_wctp_h = pan + 6*(PANEL_B/4);
    const uint32_t* p_wctp_l = pan + 7*(PANEL_B/4);

    // per-thread BN constants (channels 2t,2t+1, 8+2t, 9+2t)
    int o0 = 2*t, o1 = 2*t+1, o8 = 8+2*t, o9 = 9+2*t;
    float gd_[4]  = { s_par[P_GD+o0],  s_par[P_GD+o1],  s_par[P_GD+o8],  s_par[P_GD+o9]  };
    float bed_[4] = { s_par[P_BED+o0], s_par[P_BED+o1], s_par[P_BED+o8], s_par[P_BED+o9] };
    float gc_[4]  = { s_par[P_GC+o0],  s_par[P_GC+o1],  s_par[P_GC+o8],  s_par[P_GC+o9]  };
    float bec_[4] = { s_par[P_BEC+o0], s_par[P_BEC+o1], s_par[P_BEC+o8], s_par[P_BEC+o9] };

    // ---- a-tile conv: Dd = wdt[:,0:10](x)a ----
    float Dd[2][2][4];
    #pragma unroll
    for (int s=0;s<2;s++)
        #pragma unroll
        for (int n=0;n<2;n++)
            #pragma unroll
            for (int j=0;j<4;j++) Dd[s][n][j] = 0.0f;
    conv_hmma(Dd, (const float*)(smem + SM_T0), p_wdta_h, p_wdta_l, w, g, t, off0, off1);

    // ---- h-tile dual conv: Dd += wdt[:,10:20](x)h ; accA = wct[:,0:10](x)h ----
    float accA[2][2][4];
    #pragma unroll
    for (int s=0;s<2;s++)
        #pragma unroll
        for (int n=0;n<2;n++)
            #pragma unroll
            for (int j=0;j<4;j++) accA[s][n][j] = 0.0f;
    conv_hmma_dual(Dd, accA, (const float*)(smem + SM_T1),
                   p_wdth_h, p_wdth_l, p_wcth_h, p_wcth_l, w, g, t, off0, off1);

    // msg = relu(bn_d(Dd))  (in place)
    #pragma unroll
    for (int s=0;s<2;s++)
        #pragma unroll
        for (int n=0;n<2;n++)
            #pragma unroll
            for (int j=0;j<4;j++){
                int oi = n*2 + (j&1);
                Dd[s][n][j] = fmaxf(fmaf(gd_[oi], Dd[s][n][j], bed_[oi]), 0.0f);
            }

    __syncthreads();   // all warps done reading T0/T1 before ring reuse

    // ---- part loop (ring T2,T0,T1) ----
    const int bufoff[3] = {SM_T2, SM_T0, SM_T1};
    for (int part=0; part<nparts; part++){
        if (part+1 < nparts){
            stage_tile(smem, bufoff[(part+1)%3], g_pm + (size_t)((pidx0+part+1)*NB + b)*CHW, tid, x0, y0);
            CP_COMMIT();
            CP_WAIT1();
        } else {
            CP_WAIT0();
        }
        __syncthreads();

        float Cp[2][2][4];
        #pragma unroll
        for (int s=0;s<2;s++)
            #pragma unroll
            for (int n=0;n<2;n++)
                #pragma unroll
                for (int j=0;j<4;j++) Cp[s][n][j] = accA[s][n][j];
        conv_hmma(Cp, (const float*)(smem + bufoff[part%3]), p_wctp_h, p_wctp_l, w, g, t, off0, off1);
        #pragma unroll
        for (int s=0;s<2;s++)
            #pragma unroll
            for (int n=0;n<2;n++)
                #pragma unroll
                for (int j=0;j<4;j++){
                    int oi = n*2 + (j&1);
                    Dd[s][n][j] += fmaxf(fmaf(gc_[oi], Cp[s][n][j], bec_[oi]), 0.0f);
                }
    }

    // ---- scatter msg fragments to smem [m][out] (reuse T0 buffer) ----
    __syncthreads();   // everyone done with all tile buffers
    float* s_msg = (float*)(smem + SM_T0);
    #pragma unroll
    for (int s=0;s<2;s++){
        int m0 = w*32 + s*16 + g;
        #pragma unroll
        for (int n=0;n<2;n++){
            if (n == 0 || t == 0){
                int oc = n*8 + 2*t;
                *(float2*)&s_msg[m0*12 + oc]     = make_float2(Dd[s][n][0], Dd[s][n][1]);
                *(float2*)&s_msg[(m0+8)*12 + oc] = make_float2(Dd[s][n][2], Dd[s][n][3]);
            }
        }
    }
    __syncthreads();

    // ---------- GRU epilogue (1 px per thread) ----------
    int py = y0 + (tid >> 5), pxx = x0 + (tid & 31);
    float msg[10], hcen[10];
    #pragma unroll
    for (int c=0;c<10;c++) msg[c] = s_msg[tid*12 + c];
    {
        const float* hc = hX + (size_t)py*NW + pxx;
        #pragma unroll
        for (int c=0;c<10;c++) hcen[c] = hc[(size_t)c*HW];
    }
    float g0 = s_par[P_BG], g1 = s_par[P_BG+1];
    #pragma unroll
    for (int c=0;c<10;c++){
        g0 = fmaf(s_par[P_WG+c],    msg[c],  g0);
        g0 = fmaf(s_par[P_WG+10+c], hcen[c], g0);
        g1 = fmaf(s_par[P_WG+20+c], msg[c],  g1);
        g1 = fmaf(s_par[P_WG+30+c], hcen[c], g1);
    }
    float rr = sigmoidf_(g0), uu = sigmoidf_(g1);
    float rh[10];
    #pragma unroll
    for (int c=0;c<10;c++) rh[c] = rr*hcen[c];

    float* op = outp + (size_t)py*NW + pxx;
    #pragma unroll
    for (int o=0;o<10;o++){
        float s = 0.0f;
        #pragma unroll
        for (int c=0;c<10;c++){
            s = fmaf(s_par[P_WC + o*20 + c],      msg[c], s);
            s = fmaf(s_par[P_WC + o*20 + 10 + c], rh[c],  s);
        }
        float cn = fmaf(s_par[P_GG+o], s, s_par[P_BEG+o]);
        cn = cn > 0.0f ? cn : 0.01f*cn;
        op[(size_t)o*HW] = (1.0f-uu)*hcen[o] + uu*cn;
    }
}

// ================= launcher =================
extern "C" void kernel_launch(void* const* d_in, const int* in_sizes, int n_in,
                              void* d_out, int out_size)
{
    const float* f_nodes  = (const float*)d_in[0];
    const float* h_nodes  = (const float*)d_in[1];
    const float* p_nodes  = (const float*)d_in[2];
    const float* w_dmap   = (const float*)d_in[4];
    const float* b_dmap   = (const float*)d_in[5];
    const float* w_decomp = (const float*)d_in[6];
    const float* g_decomp = (const float*)d_in[7];
    const float* be_decomp= (const float*)d_in[8];
    const float* w_cau    = (const float*)d_in[9];
    const float* b_cau    = (const float*)d_in[10];
    const float* w_cal    = (const float*)d_in[11];
    const float* b_cal    = (const float*)d_in[12];
    const float* w_cu     = (const float*)d_in[13];
    const float* g_cu     = (const float*)d_in[14];
    const float* be_cu    = (const float*)d_in[15];
    const float* w_cl     = (const float*)d_in[16];
    const float* g_cl     = (const float*)d_in[17];
    const float* be_cl    = (const float*)d_in[18];
    const float* wg_u     = (const float*)d_in[19];
    const float* bg_u     = (const float*)d_in[20];
    const float* wc_u     = (const float*)d_in[21];
    const float* g_u      = (const float*)d_in[22];
    const float* be_u     = (const float*)d_in[23];
    const float* wg_l     = (const float*)d_in[24];
    const float* bg_l     = (const float*)d_in[25];
    const float* wc_l     = (const float*)d_in[26];
    const float* g_l      = (const float*)d_in[27];
    const float* be_l     = (const float*)d_in[28];

    float* out        = (float*)d_out;
    float* out_decomp = out + (size_t)3*NB*CHW;
    float* out_cmu    = out_decomp + (size_t)NB*3*HW;
    float* out_cml    = out_cmu + (size_t)NB*HW;

    k0_weights<<<6, 256>>>(w_decomp, w_cu, w_cl);

    k1_pointwise<<<NB*HW/1024, 256>>>(f_nodes, h_nodes, p_nodes,
                                      w_dmap, b_dmap, w_cau, b_cau, w_cal, b_cal,
                                      out_decomp, out_cmu, out_cml, out);

    static int smem_set = 0;
    if (!smem_set){
        cudaFuncSetAttribute(k2_conv, cudaFuncAttributeMaxDynamicSharedMemorySize, SMEM_BYTES);
        smem_set = 1;
    }
    dim3 g2(NW/TILE_W, NH/TILE_H, 2*NB), b2(256, 1, 1);
    k2_conv<<<g2, b2, SMEM_BYTES>>>(h_nodes,
                                    g_decomp, be_decomp,
                                    g_cu, be_cu, g_cl, be_cl,
                                    wg_u, bg_u, wc_u, g_u, be_u,
                                    wg_l, bg_l, wc_l, g_l, be_l,
                                    out);
}

// round 14
// speedup vs baseline: 1.2542x; 1.0778x over previous
#include <cuda_runtime.h>
#include <cuda_bf16.h>
#include <cstdint>

#define NB 8
#define NC 10
#define NH 192
#define NW 192
#define HW (NH*NW)
#define CHW (NC*HW)

// ---------------- k2 geometry ----------------
#define TILE_W 32
#define TILE_H 8
#define TROWP 40              /* tile row words, base gx = x0-4 */
#define TROWS 10              /* 8 + 2 halo */
#define TCI_STRIDE 400        /* TROWS * TROWP */
#define TILE_B 16000          /* 10ch * 400 * 4 bytes */
#define TILE_CHUNKS 1000      /* 16B chunks per 10-ch tile */

// weight panels: [16 outs x 168 K-halves] bf16, row stride 84 words
#define KPW 84
#define PANEL_B 5376

// smem byte layout
#define SM_PANELS 0           /* 8 local panels = 43008 */
#define SM_T0 43008
#define SM_T1 (SM_T0 + TILE_B)
#define SM_T2 (SM_T1 + TILE_B)
#define SM_PAR (SM_T2 + TILE_B)
#define SMEM_BYTES (SM_PAR + 1216)

// param offsets (floats)
#define P_GD 0
#define P_BED 10
#define P_GC 20
#define P_BEC 30
#define P_GG 40
#define P_BEG 50
#define P_WG 60
#define P_BG 100
#define P_WC 102

// ---------------- scratch (static device globals; no allocation) ----------------
// packed (hi<<16)|lo bf16 words
__device__ __align__(16) uint32_t g_a1[NB*CHW];
__device__ __align__(16) uint32_t g_a2[NB*CHW];
__device__ __align__(16) uint32_t g_pm[6*NB*CHW];
__device__ __align__(16) uint32_t g_hp[2*NB*CHW];
// 12 global panels: s=0..5 {wdt0,wdt1,wcu0,wcu1,wcl0,wcl1} x {hi,lo}
__device__ __align__(16) unsigned short g_wp[12*16*168];

__device__ __forceinline__ float sigmoidf_(float x){ return 1.0f/(1.0f+expf(-x)); }
__device__ __forceinline__ float4 f4fma(float s, float4 v, float4 a){
    return make_float4(fmaf(s,v.x,a.x), fmaf(s,v.y,a.y), fmaf(s,v.z,a.z), fmaf(s,v.w,a.w));
}
__device__ __forceinline__ float4 f4s(float s){ return make_float4(s,s,s,s); }

__device__ __forceinline__ uint32_t smem_to_u32(const void* p) {
    uint32_t a;
    asm("{ .reg .u64 t; cvta.to.shared.u64 t, %1; cvt.u32.u64 %0, t; }" : "=r"(a) : "l"(p));
    return a;
}
#define CP_COMMIT() asm volatile("cp.async.commit_group;")
#define CP_WAIT0()  asm volatile("cp.async.wait_group 0;" ::: "memory")
#define CP_WAIT1()  asm volatile("cp.async.wait_group 1;" ::: "memory")

// pack fp32 -> (truncated-bf16 hi << 16) | rn-bf16(residual)
__device__ __forceinline__ uint32_t packw(float x){
    uint32_t u = __float_as_uint(x);
    float lof = x - __uint_as_float(u & 0xffff0000u);
    __nv_bfloat16 lb = __float2bfloat16(lof);
    unsigned short ls = *(unsigned short*)&lb;
    return (u & 0xffff0000u) | (uint32_t)ls;
}
__device__ __forceinline__ uint4 packw4(float4 v){
    uint4 r;
    r.x = packw(v.x); r.y = packw(v.y); r.z = packw(v.z); r.w = packw(v.w);
    return r;
}

// ================= Kernel 1: pointwise + packing + panel prep + slot0 =================
__global__ __launch_bounds__(256) void k1_pointwise(
    const float* __restrict__ f_nodes,
    const float* __restrict__ h_nodes,
    const float* __restrict__ p_nodes,
    const float* __restrict__ w_dmap, const float* __restrict__ b_dmap,
    const float* __restrict__ w_cau,  const float* __restrict__ b_cau,
    const float* __restrict__ w_cal,  const float* __restrict__ b_cal,
    const float* __restrict__ w_decomp, const float* __restrict__ w_cu, const float* __restrict__ w_cl,
    float* __restrict__ out_decomp, float* __restrict__ out_cmu, float* __restrict__ out_cml,
    float* __restrict__ out_xh)
{
    // ---- blocks 0..5: weight panel prep (merged k0) ----
    if (blockIdx.x < 6){
        int s = blockIdx.x;
        const float* w = (s < 2) ? w_decomp : ((s < 4) ? w_cu : w_cl);
        int cibase = (s & 1) * 10;
        for (int i = threadIdx.x; i < 16*168; i += 256){
            int n = i / 168, k = i - n*168;
            float val = 0.0f;
            if (n < 10 && k < 160){
                int ci = k >> 4, tp = k & 15;
                if (tp < 9) val = w[(n*20 + cibase + ci)*9 + tp];
            }
            unsigned u = __float_as_uint(val);
            unsigned short hb = (unsigned short)(u >> 16);
            float lof = val - __uint_as_float(u & 0xffff0000u);
            __nv_bfloat16 lb = __float2bfloat16(lof);
            g_wp[(size_t)(2*s)*2688 + i]   = hb;
            g_wp[(size_t)(2*s+1)*2688 + i] = *(unsigned short*)&lb;
        }
    }

    __shared__ float s_wd[90], s_bd[3], s_wcau[40], s_wcal[20], s_bc[2];
    int t = threadIdx.x;
    if (t < 90)              s_wd[t]        = w_dmap[t];
    if (t >= 96 && t < 99)   s_bd[t-96]     = b_dmap[t-96];
    if (t >= 128 && t < 168) s_wcau[t-128]  = w_cau[t-128];
    if (t >= 192 && t < 212) s_wcal[t-192]  = w_cal[t-192];
    if (t == 224) s_bc[0] = b_cau[0];
    if (t == 225) s_bc[1] = b_cal[0];
    __syncthreads();

    int pix = (blockIdx.x*256 + t)*4;
    int b = pix / HW, p = pix - b*HW;

    const float* f1b = f_nodes + (size_t)(1*NB + b)*CHW + p;
    const float* h1b = h_nodes + (size_t)(1*NB + b)*CHW + p;
    const float* h2b = h_nodes + (size_t)(2*NB + b)*CHW + p;

    uint32_t* hp1 = g_hp + (size_t)(0*NB + b)*CHW + p;
    uint32_t* hp2 = g_hp + (size_t)(1*NB + b)*CHW + p;

    float4 f[10];
    float4 dm0 = f4s(s_bd[0]), dm1 = f4s(s_bd[1]), dm2 = f4s(s_bd[2]);
    #pragma unroll
    for (int c=0;c<10;c++){
        f[c]       = *(const float4*)(f1b + c*HW);
        float4 u1  = *(const float4*)(h1b + c*HW);
        float4 u2  = *(const float4*)(h2b + c*HW);
        *(uint4*)(hp1 + c*HW) = packw4(u1);
        *(uint4*)(hp2 + c*HW) = packw4(u2);
        dm0 = f4fma(s_wd[ 0+c],f[c],dm0); dm0 = f4fma(s_wd[10+c],u1,dm0); dm0 = f4fma(s_wd[20+c],u2,dm0);
        dm1 = f4fma(s_wd[30+c],f[c],dm1); dm1 = f4fma(s_wd[40+c],u1,dm1); dm1 = f4fma(s_wd[50+c],u2,dm1);
        dm2 = f4fma(s_wd[60+c],f[c],dm2); dm2 = f4fma(s_wd[70+c],u1,dm2); dm2 = f4fma(s_wd[80+c],u2,dm2);
    }

    float4 att1, att2;
    {
        float d0v[4] = {dm0.x,dm0.y,dm0.z,dm0.w};
        float d1v[4] = {dm1.x,dm1.y,dm1.z,dm1.w};
        float d2v[4] = {dm2.x,dm2.y,dm2.z,dm2.w};
        float a1v[4], a2v[4];
        #pragma unroll
        for (int i=0;i<4;i++){
            float mx = fmaxf(d0v[i], fmaxf(d1v[i], d2v[i]));
            float e0 = expf(d0v[i]-mx), e1 = expf(d1v[i]-mx), e2 = expf(d2v[i]-mx);
            float inv = 1.0f/(e0+e1+e2);
            a1v[i] = e1*inv; a2v[i] = e2*inv;
        }
        att1 = make_float4(a1v[0],a1v[1],a1v[2],a1v[3]);
        att2 = make_float4(a2v[0],a2v[1],a2v[2],a2v[3]);
    }

    uint32_t* a1p = g_a1 + (size_t)b*CHW + p;
    uint32_t* a2p = g_a2 + (size_t)b*CHW + p;
    #pragma unroll
    for (int c=0;c<10;c++){
        *(uint4*)(a1p + c*HW) = packw4(make_float4(f[c].x*att1.x, f[c].y*att1.y, f[c].z*att1.z, f[c].w*att1.w));
        *(uint4*)(a2p + c*HW) = packw4(make_float4(f[c].x*att2.x, f[c].y*att2.y, f[c].z*att2.z, f[c].w*att2.w));
    }

    *(float4*)(out_decomp + (size_t)(b*3+0)*HW + p) = dm0;
    *(float4*)(out_decomp + (size_t)(b*3+1)*HW + p) = dm1;
    *(float4*)(out_decomp + (size_t)(b*3+2)*HW + p) = dm2;

    float4 su = f4s(s_bc[0]);
    #pragma unroll
    for (int j=0;j<4;j++){
        const float* pp = p_nodes + (size_t)((j+1)*NB + b)*CHW + p;
        #pragma unroll
        for (int c=0;c<10;c++) su = f4fma(s_wcau[j*10+c], *(const float4*)(pp + c*HW), su);
    }
    float4 mu = make_float4(sigmoidf_(su.x), sigmoidf_(su.y), sigmoidf_(su.z), sigmoidf_(su.w));
    *(float4*)(out_cmu + (size_t)b*HW + p) = mu;

    float4 sl = f4s(s_bc[1]);
    #pragma unroll
    for (int j=0;j<2;j++){
        const float* pp = p_nodes + (size_t)((j+5)*NB + b)*CHW + p;
        #pragma unroll
        for (int c=0;c<10;c++) sl = f4fma(s_wcal[j*10+c], *(const float4*)(pp + c*HW), sl);
    }
    float4 ml = make_float4(sigmoidf_(sl.x), sigmoidf_(sl.y), sigmoidf_(sl.z), sigmoidf_(sl.w));
    *(float4*)(out_cml + (size_t)b*HW + p) = ml;

    #pragma unroll
    for (int j=0;j<4;j++){
        const float* pp = p_nodes + (size_t)((j+1)*NB + b)*CHW + p;
        uint32_t* od = g_pm + (size_t)(j*NB + b)*CHW + p;
        #pragma unroll
        for (int c=0;c<10;c++){
            float4 v = *(const float4*)(pp + c*HW);
            *(uint4*)(od + c*HW) = packw4(make_float4(v.x*mu.x, v.y*mu.y, v.z*mu.z, v.w*mu.w));
        }
    }
    #pragma unroll
    for (int j=0;j<2;j++){
        const float* pp = p_nodes + (size_t)((j+5)*NB + b)*CHW + p;
        uint32_t* od = g_pm + (size_t)((4+j)*NB + b)*CHW + p;
        #pragma unroll
        for (int c=0;c<10;c++){
            float4 v = *(const float4*)(pp + c*HW);
            *(uint4*)(od + c*HW) = packw4(make_float4(v.x*ml.x, v.y*ml.y, v.z*ml.z, v.w*ml.w));
        }
    }

    const float* h0 = h_nodes + (size_t)b*CHW + p;
    float* o0 = out_xh + (size_t)b*CHW + p;
    #pragma unroll
    for (int c=0;c<10;c++) *(float4*)(o0 + c*HW) = *(const float4*)(h0 + c*HW);
}

// ================= Kernel 2 helpers =================
__device__ __forceinline__ void stage_tile(char* smembase, int toff, const uint32_t* __restrict__ src,
                                           int tid, int x0, int y0)
{
    unsigned sbase = smem_to_u32(smembase + toff);
    #pragma unroll
    for (int j=0;j<4;j++){
        int i = tid + j*256;
        if (i < TILE_CHUNKS){
            int ci = i/100, rem = i - ci*100;
            int r = rem/10, c4 = rem - r*10;
            int gy = y0-1+r, gx = x0-4+c4*4;
            bool in = (gy>=0) & (gy<NH) & (gx>=0) & (gx<NW);
            const uint32_t* g = src + (size_t)ci*HW + (in ? (gy*NW+gx) : 0);
            unsigned d = sbase + (unsigned)((ci*TCI_STRIDE + r*TROWP + c4*4)*4);
            int ssz = in ? 16 : 0;
            asm volatile("cp.async.cg.shared.global [%0], [%1], 16, %2;" :: "r"(d), "l"(g), "r"(ssz));
        }
    }
}

#define PRMT(d, a, b, m) asm("prmt.b32 %0, %1, %2, %3;" : "=r"(d) : "r"(a), "r"(b), "n"(m))

#define MMA_BF16(c, a0,a1,a2,a3, b0,b1) \
    asm volatile("mma.sync.aligned.m16n8k16.row.col.f32.bf16.bf16.f32 " \
        "{%0,%1,%2,%3}, {%4,%5,%6,%7}, {%8,%9}, {%0,%1,%2,%3};" \
        : "+f"((c)[0]), "+f"((c)[1]), "+f"((c)[2]), "+f"((c)[3]) \
        : "r"(a0), "r"(a1), "r"(a2), "r"(a3), "r"(b0), "r"(b1))

// one conv (implicit GEMM, split bf16 x3 terms) from PRE-PACKED tiles
__device__ __forceinline__ void conv_hmma(
    float C[2][2][4], const uint32_t* tile,
    const uint32_t* ph, const uint32_t* pl,
    int w, int g, int t, int off0, int off1)
{
    #pragma unroll 1
    for (int ci=0; ci<10; ci++){
        uint32_t bh0[2], bh1[2], bl0[2], bl1[2];
        #pragma unroll
        for (int n=0;n<2;n++){
            int bi = (n*8+g)*KPW + ci*8 + t;
            bh0[n]=ph[bi]; bh1[n]=ph[bi+4];
            bl0[n]=pl[bi]; bl1[n]=pl[bi+4];
        }
        const uint32_t* f = tile + ci*TCI_STRIDE + w*TROWP + g + 3;
        #pragma unroll
        for (int s=0;s<2;s++){
            const uint32_t* fs = f + 16*s;
            uint32_t v0w=fs[off0], v1w=fs[off1], w0w=fs[off0+8], w1w=fs[off1+8];
            uint32_t v8w=fs[82], w8w=fs[90];
            uint32_t ah0, al0, ah1, al1, ah2, al2, ah3, al3;
            PRMT(ah0, v0w, v1w, 0x7632); PRMT(al0, v0w, v1w, 0x5410);
            PRMT(ah1, w0w, w1w, 0x7632); PRMT(al1, w0w, w1w, 0x5410);
            PRMT(ah2, v8w, 0u, 0x7632);  PRMT(al2, v8w, 0u, 0x5410);
            PRMT(ah3, w8w, 0u, 0x7632);  PRMT(al3, w8w, 0u, 0x5410);
            if (t != 0){ ah2=0u; al2=0u; ah3=0u; al3=0u; }
            #pragma unroll
            for (int n=0;n<2;n++){
                MMA_BF16(C[s][n], ah0,ah1,ah2,ah3, bh0[n], bh1[n]);  // hi*hi
                MMA_BF16(C[s][n], al0,al1,al2,al3, bh0[n], bh1[n]);  // lo*hi
                MMA_BF16(C[s][n], ah0,ah1,ah2,ah3, bl0[n], bl1[n]);  // hi*lo
            }
        }
    }
}

// dual: same A fragments feed two accumulator/panel sets (h tile shared)
__device__ __forceinline__ void conv_hmma_dual(
    float C1[2][2][4], float C2[2][2][4], const uint32_t* tile,
    const uint32_t* p1h, const uint32_t* p1l,
    const uint32_t* p2h, const uint32_t* p2l,
    int w, int g, int t, int off0, int off1)
{
    #pragma unroll 1
    for (int ci=0; ci<10; ci++){
        uint32_t b1h0[2], b1h1[2], b1l0[2], b1l1[2];
        uint32_t b2h0[2], b2h1[2], b2l0[2], b2l1[2];
        #pragma unroll
        for (int n=0;n<2;n++){
            int bi = (n*8+g)*KPW + ci*8 + t;
            b1h0[n]=p1h[bi]; b1h1[n]=p1h[bi+4];
            b1l0[n]=p1l[bi]; b1l1[n]=p1l[bi+4];
            b2h0[n]=p2h[bi]; b2h1[n]=p2h[bi+4];
            b2l0[n]=p2l[bi]; b2l1[n]=p2l[bi+4];
        }
        const uint32_t* f = tile + ci*TCI_STRIDE + w*TROWP + g + 3;
        #pragma unroll
        for (int s=0;s<2;s++){
            const uint32_t* fs = f + 16*s;
            uint32_t v0w=fs[off0], v1w=fs[off1], w0w=fs[off0+8], w1w=fs[off1+8];
            uint32_t v8w=fs[82], w8w=fs[90];
            uint32_t ah0, al0, ah1, al1, ah2, al2, ah3, al3;
            PRMT(ah0, v0w, v1w, 0x7632); PRMT(al0, v0w, v1w, 0x5410);
            PRMT(ah1, w0w, w1w, 0x7632); PRMT(al1, w0w, w1w, 0x5410);
            PRMT(ah2, v8w, 0u, 0x7632);  PRMT(al2, v8w, 0u, 0x5410);
            PRMT(ah3, w8w, 0u, 0x7632);  PRMT(al3, w8w, 0u, 0x5410);
            if (t != 0){ ah2=0u; al2=0u; ah3=0u; al3=0u; }
            #pragma unroll
            for (int n=0;n<2;n++){
                MMA_BF16(C1[s][n], ah0,ah1,ah2,ah3, b1h0[n], b1h1[n]);
                MMA_BF16(C1[s][n], al0,al1,al2,al3, b1h0[n], b1h1[n]);
                MMA_BF16(C1[s][n], ah0,ah1,ah2,ah3, b1l0[n], b1l1[n]);
                MMA_BF16(C2[s][n], ah0,ah1,ah2,ah3, b2h0[n], b2h1[n]);
                MMA_BF16(C2[s][n], al0,al1,al2,al3, b2h0[n], b2h1[n]);
                MMA_BF16(C2[s][n], ah0,ah1,ah2,ah3, b2l0[n], b2l1[n]);
            }
        }
    }
}

// ================= Kernel 2: HMMA fused convs + GRU =================
__global__ __launch_bounds__(256,2) void k2_conv(
    const float* __restrict__ h_nodes,
    const float* __restrict__ g_decomp, const float* __restrict__ be_decomp,
    const float* __restrict__ g_cu, const float* __restrict__ be_cu,
    const float* __restrict__ g_cl, const float* __restrict__ be_cl,
    const float* __restrict__ wg_u, const float* __restrict__ bg_u,
    const float* __restrict__ wc_u, const float* __restrict__ g_u, const float* __restrict__ be_u,
    const float* __restrict__ wg_l, const float* __restrict__ bg_l,
    const float* __restrict__ wc_l, const float* __restrict__ g_l, const float* __restrict__ be_l,
    float* __restrict__ out_xh)
{
    extern __shared__ __align__(16) char smem[];
    float* s_par = (float*)(smem + SM_PAR);

    int z = blockIdx.z; int b = z >> 1; int half = z & 1;
    const float* gcv  = half ? g_cl  : g_cu;
    const float* becv = half ? be_cl : be_cu;
    const uint32_t* aX  = (half ? g_a2 : g_a1) + (size_t)b*CHW;
    const uint32_t* hpX = g_hp + (size_t)(half*NB + b)*CHW;
    const float* hX   = h_nodes + (size_t)((half?2:1)*NB + b)*CHW;
    const float* wgv  = half ? wg_l : wg_u;
    const float* bgv  = half ? bg_l : bg_u;
    const float* wcv  = half ? wc_l : wc_u;
    const float* ggv  = half ? g_l  : g_u;
    const float* bev  = half ? be_l : be_u;
    float* outp       = out_xh + (size_t)((half?2:1)*NB + b)*CHW;
    int nparts = half ? 2 : 4;
    int pidx0  = half ? 4 : 0;

    int tid = threadIdx.x;
    int w = tid >> 5, lane = tid & 31;
    int g = lane >> 2, t = lane & 3;
    int x0 = blockIdx.x*TILE_W, y0 = blockIdx.y*TILE_H;

    int tp0 = 2*t, tp1 = 2*t+1;
    int dy0 = tp0/3, dx0 = tp0 - 3*dy0;
    int dy1 = tp1/3, dx1 = tp1 - 3*dy1;
    int off0 = dy0*TROWP + dx0, off1 = dy1*TROWP + dx1;

    // ---- issue panel + a/h tile cp.async (one group) ----
    {
        unsigned sb = smem_to_u32(smem);
        #pragma unroll
        for (int j=0;j<11;j++){
            int i = tid + j*256;
            if (i < 2688){
                int lp = i / 336, within = i - lp*336;
                int gp = (lp < 4) ? lp : ((half ? 8 : 4) + (lp-4));
                const char* gsrc = (const char*)g_wp + (size_t)gp*PANEL_B + within*16;
                unsigned d = sb + (unsigned)(SM_PANELS + lp*PANEL_B + within*16);
                asm volatile("cp.async.cg.shared.global [%0], [%1], 16;" :: "r"(d), "l"(gsrc));
            }
        }
        stage_tile(smem, SM_T0, aX, tid, x0, y0);
        stage_tile(smem, SM_T1, hpX, tid, x0, y0);
        CP_COMMIT();
    }

    // ---- params ----
    if (tid < 10){
        s_par[P_GD+tid]=g_decomp[tid]; s_par[P_BED+tid]=be_decomp[tid];
        s_par[P_GC+tid]=gcv[tid];      s_par[P_BEC+tid]=becv[tid];
        s_par[P_GG+tid]=ggv[tid];      s_par[P_BEG+tid]=bev[tid];
    }
    if (tid >= 32 && tid < 72) s_par[P_WG + tid-32] = wgv[tid-32];
    if (tid == 72) { s_par[P_BG]=bgv[0]; s_par[P_BG+1]=bgv[1]; }
    if (tid < 100){ s_par[P_WC+tid] = wcv[tid]; s_par[P_WC+100+tid] = wcv[100+tid]; }

    CP_WAIT0();
    __syncthreads();

    // issue part0 -> T2
    stage_tile(smem, SM_T2, g_pm + (size_t)(pidx0*NB + b)*CHW, tid, x0, y0);
    CP_COMMIT();

    const uint32_t* pan = (const uint32_t*)(smem + SM_PANELS);
    const uint32_t* p_wdta_h = pan + 0*(PANEL_B/4);
    const uint32_t* p_wdta_l = pan + 1*(PANEL_B/4);
    const uint32_t* p_wdth_h = pan + 2*(PANEL_B/4);
    const uint32_t* p_wdth_l = pan + 3*(PANEL_B/4);
    const uint32_t* p_wcth_h = pan + 4*(PANEL_B/4);
    const uint32_t* p_wcth_l = pan + 5*(PANEL_B/4);
    const uint32_t* p_wctp_h = pan + 6*(PANEL_B/4);
    const uint32_t* p_wctp_l = pan + 7*(PANEL_B/4);

    int o0 = 2*t, o1 = 2*t+1, o8 = 8+2*t, o9 = 9+2*t;
    float gd_[4]  = { s_par[P_GD+o0],  s_par[P_GD+o1],  s_par[P_GD+o8],  s_par[P_GD+o9]  };
    float bed_[4] = { s_par[P_BED+o0], s_par[P_BED+o1], s_par[P_BED+o8], s_par[P_BED+o9] };
    float gc_[4]  = { s_par[P_GC+o0],  s_par[P_GC+o1],  s_par[P_GC+o8],  s_par[P_GC+o9]  };
    float bec_[4] = { s_par[P_BEC+o0], s_par[P_BEC+o1], s_par[P_BEC+o8], s_par[P_BEC+o9] };

    // ---- a-tile conv: Dd = wdt[:,0:10](x)a ----
    float Dd[2][2][4];
    #pragma unroll
    for (int s=0;s<2;s++)
        #pragma unroll
        for (int n=0;n<2;n++)
            #pragma unroll
            for (int j=0;j<4;j++) Dd[s][n][j] = 0.0f;
    conv_hmma(Dd, (const uint32_t*)(smem + SM_T0), p_wdta_h, p_wdta_l, w, g, t, off0, off1);

    // ---- h-tile dual conv ----
    float accA[2][2][4];
    #pragma unroll
    for (int s=0;s<2;s++)
        #pragma unroll
        for (int n=0;n<2;n++)
            #pragma unroll
            for (int j=0;j<4;j++) accA[s][n][j] = 0.0f;
    conv_hmma_dual(Dd, accA, (const uint32_t*)(smem + SM_T1),
                   p_wdth_h, p_wdth_l, p_wcth_h, p_wcth_l, w, g, t, off0, off1);

    #pragma unroll
    for (int s=0;s<2;s++)
        #pragma unroll
        for (int n=0;n<2;n++)
            #pragma unroll
            for (int j=0;j<4;j++){
                int oi = n*2 + (j&1);
                Dd[s][n][j] = fmaxf(fmaf(gd_[oi], Dd[s][n][j], bed_[oi]), 0.0f);
            }

    __syncthreads();   // all warps done reading T0/T1 before ring reuse

    // ---- part loop (ring T2,T0,T1) ----
    const int bufoff[3] = {SM_T2, SM_T0, SM_T1};
    for (int part=0; part<nparts; part++){
        if (part+1 < nparts){
            stage_tile(smem, bufoff[(part+1)%3], g_pm + (size_t)((pidx0+part+1)*NB + b)*CHW, tid, x0, y0);
            CP_COMMIT();
            CP_WAIT1();
        } else {
            CP_WAIT0();
        }
        __syncthreads();

        float Cp[2][2][4];
        #pragma unroll
        for (int s=0;s<2;s++)
            #pragma unroll
            for (int n=0;n<2;n++)
                #pragma unroll
                for (int j=0;j<4;j++) Cp[s][n][j] = accA[s][n][j];
        conv_hmma(Cp, (const uint32_t*)(smem + bufoff[part%3]), p_wctp_h, p_wctp_l, w, g, t, off0, off1);
        #pragma unroll
        for (int s=0;s<2;s++)
            #pragma unroll
            for (int n=0;n<2;n++)
                #pragma unroll
                for (int j=0;j<4;j++){
                    int oi = n*2 + (j&1);
                    Dd[s][n][j] += fmaxf(fmaf(gc_[oi], Cp[s][n][j], bec_[oi]), 0.0f);
                }
    }

    // ---- scatter msg fragments to smem (reuse T0) ----
    __syncthreads();
    float* s_msg = (float*)(smem + SM_T0);
    #pragma unroll
    for (int s=0;s<2;s++){
        int m0 = w*32 + s*16 + g;
        #pragma unroll
        for (int n=0;n<2;n++){
            if (n == 0 || t == 0){
                int oc = n*8 + 2*t;
                *(float2*)&s_msg[m0*12 + oc]     = make_float2(Dd[s][n][0], Dd[s][n][1]);
                *(float2*)&s_msg[(m0+8)*12 + oc] = make_float2(Dd[s][n][2], Dd[s][n][3]);
            }
        }
    }
    __syncthreads();

    // ---------- GRU epilogue (1 px per thread) ----------
    int py = y0 + (tid >> 5), pxx = x0 + (tid & 31);
    float msg[10], hcen[10];
    #pragma unroll
    for (int c=0;c<10;c++) msg[c] = s_msg[tid*12 + c];
    {
        const float* hc = hX + (size_t)py*NW + pxx;
        #pragma unroll
        for (int c=0;c<10;c++) hcen[c] = hc[(size_t)c*HW];
    }
    float g0 = s_par[P_BG], g1 = s_par[P_BG+1];
    #pragma unroll
    for (int c=0;c<10;c++){
        g0 = fmaf(s_par[P_WG+c],    msg[c],  g0);
        g0 = fmaf(s_par[P_WG+10+c], hcen[c], g0);
        g1 = fmaf(s_par[P_WG+20+c], msg[c],  g1);
        g1 = fmaf(s_par[P_WG+30+c], hcen[c], g1);
    }
    float rr = sigmoidf_(g0), uu = sigmoidf_(g1);
    float rh[10];
    #pragma unroll
    for (int c=0;c<10;c++) rh[c] = rr*hcen[c];

    float* op = outp + (size_t)py*NW + pxx;
    #pragma unroll
    for (int o=0;o<10;o++){
        float s = 0.0f;
        #pragma unroll
        for (int c=0;c<10;c++){
            s = fmaf(s_par[P_WC + o*20 + c],      msg[c], s);
            s = fmaf(s_par[P_WC + o*20 + 10 + c], rh[c],  s);
        }
        float cn = fmaf(s_par[P_GG+o], s, s_par[P_BEG+o]);
        cn = cn > 0.0f ? cn : 0.01f*cn;
        op[(size_t)o*HW] = (1.0f-uu)*hcen[o] + uu*cn;
    }
}

// ================= launcher =================
extern "C" void kernel_launch(void* const* d_in, const int* in_sizes, int n_in,
                              void* d_out, int out_size)
{
    const float* f_nodes  = (const float*)d_in[0];
    const float* h_nodes  = (const float*)d_in[1];
    const float* p_nodes  = (const float*)d_in[2];
    const float* w_dmap   = (const float*)d_in[4];
    const float* b_dmap   = (const float*)d_in[5];
    const float* w_decomp = (const float*)d_in[6];
    const float* g_decomp = (const float*)d_in[7];
    const float* be_decomp= (const float*)d_in[8];
    const float* w_cau    = (const float*)d_in[9];
    const float* b_cau    = (const float*)d_in[10];
    const float* w_cal    = (const float*)d_in[11];
    const float* b_cal    = (const float*)d_in[12];
    const float* w_cu     = (const float*)d_in[13];
    const float* g_cu     = (const float*)d_in[14];
    const float* be_cu    = (const float*)d_in[15];
    const float* w_cl     = (const float*)d_in[16];
    const float* g_cl     = (const float*)d_in[17];
    const float* be_cl    = (const float*)d_in[18];
    const float* wg_u     = (const float*)d_in[19];
    const float* bg_u     = (const float*)d_in[20];
    const float* wc_u     = (const float*)d_in[21];
    const float* g_u      = (const float*)d_in[22];
    const float* be_u     = (const float*)d_in[23];
    const float* wg_l     = (const float*)d_in[24];
    const float* bg_l     = (const float*)d_in[25];
    const float* wc_l     = (const float*)d_in[26];
    const float* g_l      = (const float*)d_in[27];
    const float* be_l     = (const float*)d_in[28];

    float* out        = (float*)d_out;
    float* out_decomp = out + (size_t)3*NB*CHW;
    float* out_cmu    = out_decomp + (size_t)NB*3*HW;
    float* out_cml    = out_cmu + (size_t)NB*HW;

    k1_pointwise<<<NB*HW/1024, 256>>>(f_nodes, h_nodes, p_nodes,
                                      w_dmap, b_dmap, w_cau, b_cau, w_cal, b_cal,
                                      w_decomp, w_cu, w_cl,
                                      out_decomp, out_cmu, out_cml, out);

    static int smem_set = 0;
    if (!smem_set){
        cudaFuncSetAttribute(k2_conv, cudaFuncAttributeMaxDynamicSharedMemorySize, SMEM_BYTES);
        smem_set = 1;
    }
    dim3 g2(NW/TILE_W, NH/TILE_H, 2*NB), b2(256, 1, 1);
    k2_conv<<<g2, b2, SMEM_BYTES>>>(h_nodes,
                                    g_decomp, be_decomp,
                                    g_cu, be_cu, g_cl, be_cl,
                                    wg_u, bg_u, wc_u, g_u, be_u,
                                    wg_l, bg_l, wc_l, g_l, be_l,
                                    out);
}

// round 15
// speedup vs baseline: 1.5268x; 1.2174x over previous
#include <cuda_runtime.h>
#include <cuda_bf16.h>
#include <cstdint>

#define NB 8
#define NC 10
#define NH 192
#define NW 192
#define HW (NH*NW)
#define CHW (NC*HW)

// ---------------- k2 geometry ----------------
#define TILE_W 32
#define TILE_H 8
#define TROWP 40              /* tile row words, base gx = x0-4 */
#define TROWS 10              /* 8 + 2 halo */
#define TCI_STRIDE 400        /* TROWS * TROWP */
#define TILE_B 16000          /* 10ch * 400 * 4 bytes */
#define TILE_CHUNKS 1000      /* 16B chunks per 10-ch tile */

// weight panels: [16 outs x 96 K] bf16, row stride 52 words (104 shorts), conflict-free
#define KPW 52
#define PANEL_SH 1664         /* 16*104 shorts */
#define PANEL_B 3328          /* bytes */
#define PANEL_CHUNKS 208      /* 16B chunks */

// smem byte layout
#define SM_PANELS 0           /* 8 local panels = 26624 */
#define SM_T0 26624
#define SM_T1 (SM_T0 + TILE_B)
#define SM_T2 (SM_T1 + TILE_B)
#define SM_PAR (SM_T2 + TILE_B)   /* 74624 */
#define SMEM_BYTES (SM_PAR + 1216)

// param offsets (floats)
#define P_GD 0
#define P_BED 10
#define P_GC 20
#define P_BEC 30
#define P_GG 40
#define P_BEG 50
#define P_WG 60
#define P_BG 100
#define P_WC 102

// ---------------- scratch (static device globals; no allocation) ----------------
// packed (hi<<16)|lo bf16 words
__device__ __align__(16) uint32_t g_a1[NB*CHW];
__device__ __align__(16) uint32_t g_a2[NB*CHW];
__device__ __align__(16) uint32_t g_pm[6*NB*CHW];
__device__ __align__(16) uint32_t g_hp[2*NB*CHW];
// 12 global panels: s=0..5 {wdt0,wdt1,wcu0,wcu1,wcl0,wcl1} x {hi,lo}
__device__ __align__(16) unsigned short g_wp[12*PANEL_SH];

__device__ __forceinline__ float sigmoidf_(float x){ return 1.0f/(1.0f+expf(-x)); }
__device__ __forceinline__ float4 f4fma(float s, float4 v, float4 a){
    return make_float4(fmaf(s,v.x,a.x), fmaf(s,v.y,a.y), fmaf(s,v.z,a.z), fmaf(s,v.w,a.w));
}
__device__ __forceinline__ float4 f4s(float s){ return make_float4(s,s,s,s); }

__device__ __forceinline__ uint32_t smem_to_u32(const void* p) {
    uint32_t a;
    asm("{ .reg .u64 t; cvta.to.shared.u64 t, %1; cvt.u32.u64 %0, t; }" : "=r"(a) : "l"(p));
    return a;
}
#define CP_COMMIT() asm volatile("cp.async.commit_group;")
#define CP_WAIT0()  asm volatile("cp.async.wait_group 0;" ::: "memory")
#define CP_WAIT1()  asm volatile("cp.async.wait_group 1;" ::: "memory")

// pack fp32 -> (truncated-bf16 hi << 16) | rn-bf16(residual)
__device__ __forceinline__ uint32_t packw(float x){
    uint32_t u = __float_as_uint(x);
    float lof = x - __uint_as_float(u & 0xffff0000u);
    __nv_bfloat16 lb = __float2bfloat16(lof);
    unsigned short ls = *(unsigned short*)&lb;
    return (u & 0xffff0000u) | (uint32_t)ls;
}
__device__ __forceinline__ uint4 packw4(float4 v){
    uint4 r;
    r.x = packw(v.x); r.y = packw(v.y); r.z = packw(v.z); r.w = packw(v.w);
    return r;
}

// ================= Kernel 1: pointwise + packing + panel prep + slot0 =================
__global__ __launch_bounds__(256) void k1_pointwise(
    const float* __restrict__ f_nodes,
    const float* __restrict__ h_nodes,
    const float* __restrict__ p_nodes,
    const float* __restrict__ w_dmap, const float* __restrict__ b_dmap,
    const float* __restrict__ w_cau,  const float* __restrict__ b_cau,
    const float* __restrict__ w_cal,  const float* __restrict__ b_cal,
    const float* __restrict__ w_decomp, const float* __restrict__ w_cu, const float* __restrict__ w_cl,
    float* __restrict__ out_decomp, float* __restrict__ out_cmu, float* __restrict__ out_cml,
    float* __restrict__ out_xh)
{
    // ---- blocks 0..5: weight panel prep (K=96 compact layout) ----
    // chunk c<5: k0..7 = ci=2c taps0..7, k8..15 = ci=2c+1 taps0..7
    // chunk 5:   k0..9 = ci 0..9 tap8, rest zero
    if (blockIdx.x < 6){
        int s = blockIdx.x;
        const float* w = (s < 2) ? w_decomp : ((s < 4) ? w_cu : w_cl);
        int cibase = (s & 1) * 10;
        for (int i = threadIdx.x; i < PANEL_SH; i += 256){
            int n = i / 104, kk = i - n*104;
            float val = 0.0f;
            if (n < 10 && kk < 96){
                int c = kk >> 4, j = kk & 15;
                int ci = -1, tap = 0;
                if (c < 5){ ci = 2*c + (j >> 3); tap = j & 7; }
                else if (j < 10){ ci = j; tap = 8; }
                if (ci >= 0) val = w[(n*20 + cibase + ci)*9 + tap];
            }
            unsigned u = __float_as_uint(val);
            unsigned short hb = (unsigned short)(u >> 16);
            float lof = val - __uint_as_float(u & 0xffff0000u);
            __nv_bfloat16 lb = __float2bfloat16(lof);
            g_wp[(size_t)(2*s)*PANEL_SH + i]   = hb;
            g_wp[(size_t)(2*s+1)*PANEL_SH + i] = *(unsigned short*)&lb;
        }
    }

    __shared__ float s_wd[90], s_bd[3], s_wcau[40], s_wcal[20], s_bc[2];
    int t = threadIdx.x;
    if (t < 90)              s_wd[t]        = w_dmap[t];
    if (t >= 96 && t < 99)   s_bd[t-96]     = b_dmap[t-96];
    if (t >= 128 && t < 168) s_wcau[t-128]  = w_cau[t-128];
    if (t >= 192 && t < 212) s_wcal[t-192]  = w_cal[t-192];
    if (t == 224) s_bc[0] = b_cau[0];
    if (t == 225) s_bc[1] = b_cal[0];
    __syncthreads();

    int pix = (blockIdx.x*256 + t)*4;
    int b = pix / HW, p = pix - b*HW;

    const float* f1b = f_nodes + (size_t)(1*NB + b)*CHW + p;
    const float* h1b = h_nodes + (size_t)(1*NB + b)*CHW + p;
    const float* h2b = h_nodes + (size_t)(2*NB + b)*CHW + p;

    uint32_t* hp1 = g_hp + (size_t)(0*NB + b)*CHW + p;
    uint32_t* hp2 = g_hp + (size_t)(1*NB + b)*CHW + p;

    float4 f[10];
    float4 dm0 = f4s(s_bd[0]), dm1 = f4s(s_bd[1]), dm2 = f4s(s_bd[2]);
    #pragma unroll
    for (int c=0;c<10;c++){
        f[c]       = *(const float4*)(f1b + c*HW);
        float4 u1  = *(const float4*)(h1b + c*HW);
        float4 u2  = *(const float4*)(h2b + c*HW);
        *(uint4*)(hp1 + c*HW) = packw4(u1);
        *(uint4*)(hp2 + c*HW) = packw4(u2);
        dm0 = f4fma(s_wd[ 0+c],f[c],dm0); dm0 = f4fma(s_wd[10+c],u1,dm0); dm0 = f4fma(s_wd[20+c],u2,dm0);
        dm1 = f4fma(s_wd[30+c],f[c],dm1); dm1 = f4fma(s_wd[40+c],u1,dm1); dm1 = f4fma(s_wd[50+c],u2,dm1);
        dm2 = f4fma(s_wd[60+c],f[c],dm2); dm2 = f4fma(s_wd[70+c],u1,dm2); dm2 = f4fma(s_wd[80+c],u2,dm2);
    }

    float4 att1, att2;
    {
        float d0v[4] = {dm0.x,dm0.y,dm0.z,dm0.w};
        float d1v[4] = {dm1.x,dm1.y,dm1.z,dm1.w};
        float d2v[4] = {dm2.x,dm2.y,dm2.z,dm2.w};
        float a1v[4], a2v[4];
        #pragma unroll
        for (int i=0;i<4;i++){
            float mx = fmaxf(d0v[i], fmaxf(d1v[i], d2v[i]));
            float e0 = expf(d0v[i]-mx), e1 = expf(d1v[i]-mx), e2 = expf(d2v[i]-mx);
            float inv = 1.0f/(e0+e1+e2);
            a1v[i] = e1*inv; a2v[i] = e2*inv;
        }
        att1 = make_float4(a1v[0],a1v[1],a1v[2],a1v[3]);
        att2 = make_float4(a2v[0],a2v[1],a2v[2],a2v[3]);
    }

    uint32_t* a1p = g_a1 + (size_t)b*CHW + p;
    uint32_t* a2p = g_a2 + (size_t)b*CHW + p;
    #pragma unroll
    for (int c=0;c<10;c++){
        *(uint4*)(a1p + c*HW) = packw4(make_float4(f[c].x*att1.x, f[c].y*att1.y, f[c].z*att1.z, f[c].w*att1.w));
        *(uint4*)(a2p + c*HW) = packw4(make_float4(f[c].x*att2.x, f[c].y*att2.y, f[c].z*att2.z, f[c].w*att2.w));
    }

    *(float4*)(out_decomp + (size_t)(b*3+0)*HW + p) = dm0;
    *(float4*)(out_decomp + (size_t)(b*3+1)*HW + p) = dm1;
    *(float4*)(out_decomp + (size_t)(b*3+2)*HW + p) = dm2;

    float4 su = f4s(s_bc[0]);
    #pragma unroll
    for (int j=0;j<4;j++){
        const float* pp = p_nodes + (size_t)((j+1)*NB + b)*CHW + p;
        #pragma unroll
        for (int c=0;c<10;c++) su = f4fma(s_wcau[j*10+c], *(const float4*)(pp + c*HW), su);
    }
    float4 mu = make_float4(sigmoidf_(su.x), sigmoidf_(su.y), sigmoidf_(su.z), sigmoidf_(su.w));
    *(float4*)(out_cmu + (size_t)b*HW + p) = mu;

    float4 sl = f4s(s_bc[1]);
    #pragma unroll
    for (int j=0;j<2;j++){
        const float* pp = p_nodes + (size_t)((j+5)*NB + b)*CHW + p;
        #pragma unroll
        for (int c=0;c<10;c++) sl = f4fma(s_wcal[j*10+c], *(const float4*)(pp + c*HW), sl);
    }
    float4 ml = make_float4(sigmoidf_(sl.x), sigmoidf_(sl.y), sigmoidf_(sl.z), sigmoidf_(sl.w));
    *(float4*)(out_cml + (size_t)b*HW + p) = ml;

    #pragma unroll
    for (int j=0;j<4;j++){
        const float* pp = p_nodes + (size_t)((j+1)*NB + b)*CHW + p;
        uint32_t* od = g_pm + (size_t)(j*NB + b)*CHW + p;
        #pragma unroll
        for (int c=0;c<10;c++){
            float4 v = *(const float4*)(pp + c*HW);
            *(uint4*)(od + c*HW) = packw4(make_float4(v.x*mu.x, v.y*mu.y, v.z*mu.z, v.w*mu.w));
        }
    }
    #pragma unroll
    for (int j=0;j<2;j++){
        const float* pp = p_nodes + (size_t)((j+5)*NB + b)*CHW + p;
        uint32_t* od = g_pm + (size_t)((4+j)*NB + b)*CHW + p;
        #pragma unroll
        for (int c=0;c<10;c++){
            float4 v = *(const float4*)(pp + c*HW);
            *(uint4*)(od + c*HW) = packw4(make_float4(v.x*ml.x, v.y*ml.y, v.z*ml.z, v.w*ml.w));
        }
    }

    const float* h0 = h_nodes + (size_t)b*CHW + p;
    float* o0 = out_xh + (size_t)b*CHW + p;
    #pragma unroll
    for (int c=0;c<10;c++) *(float4*)(o0 + c*HW) = *(const float4*)(h0 + c*HW);
}

// ================= Kernel 2 helpers =================
__device__ __forceinline__ void stage_tile(char* smembase, int toff, const uint32_t* __restrict__ src,
                                           int tid, int x0, int y0)
{
    unsigned sbase = smem_to_u32(smembase + toff);
    #pragma unroll
    for (int j=0;j<4;j++){
        int i = tid + j*256;
        if (i < TILE_CHUNKS){
            int ci = i/100, rem = i - ci*100;
            int r = rem/10, c4 = rem - r*10;
            int gy = y0-1+r, gx = x0-4+c4*4;
            bool in = (gy>=0) & (gy<NH) & (gx>=0) & (gx<NW);
            const uint32_t* g = src + (size_t)ci*HW + (in ? (gy*NW+gx) : 0);
            unsigned d = sbase + (unsigned)((ci*TCI_STRIDE + r*TROWP + c4*4)*4);
            int ssz = in ? 16 : 0;
            asm volatile("cp.async.cg.shared.global [%0], [%1], 16, %2;" :: "r"(d), "l"(g), "r"(ssz));
        }
    }
}

#define PRMT(d, a, b, m) asm("prmt.b32 %0, %1, %2, %3;" : "=r"(d) : "r"(a), "r"(b), "n"(m))

#define MMA_BF16(c, a0,a1,a2,a3, b0,b1) \
    asm volatile("mma.sync.aligned.m16n8k16.row.col.f32.bf16.bf16.f32 " \
        "{%0,%1,%2,%3}, {%4,%5,%6,%7}, {%8,%9}, {%0,%1,%2,%3};" \
        : "+f"((c)[0]), "+f"((c)[1]), "+f"((c)[2]), "+f"((c)[3]) \
        : "r"(a0), "r"(a1), "r"(a2), "r"(a3), "r"(b0), "r"(b1))

// one conv: K=96 compact layout (5 even/odd-ci chunks + 1 tap8 chunk), 3-term split
__device__ __forceinline__ void conv_hmma(
    float C[2][2][4], const uint32_t* tile,
    const uint32_t* ph, const uint32_t* pl,
    int w, int g, int t, int off0, int off1)
{
    #pragma unroll 1
    for (int c=0; c<5; c++){
        uint32_t bh0[2], bh1[2], bl0[2], bl1[2];
        #pragma unroll
        for (int n=0;n<2;n++){
            int bi = (n*8+g)*KPW + c*8 + t;
            bh0[n]=ph[bi]; bh1[n]=ph[bi+4];
            bl0[n]=pl[bi]; bl1[n]=pl[bi+4];
        }
        const uint32_t* fe = tile + (2*c)*TCI_STRIDE + w*TROWP + g + 3;
        #pragma unroll
        for (int s=0;s<2;s++){
            const uint32_t* fs = fe + 16*s;
            const uint32_t* fo = fs + TCI_STRIDE;
            uint32_t e0=fs[off0], e1=fs[off1], e2=fs[off0+8], e3=fs[off1+8];
            uint32_t q0=fo[off0], q1=fo[off1], q2=fo[off0+8], q3=fo[off1+8];
            uint32_t ah0,al0,ah1,al1,ah2,al2,ah3,al3;
            PRMT(ah0, e0, e1, 0x7632); PRMT(al0, e0, e1, 0x5410);
            PRMT(ah1, e2, e3, 0x7632); PRMT(al1, e2, e3, 0x5410);
            PRMT(ah2, q0, q1, 0x7632); PRMT(al2, q0, q1, 0x5410);
            PRMT(ah3, q2, q3, 0x7632); PRMT(al3, q2, q3, 0x5410);
            #pragma unroll
            for (int n=0;n<2;n++){
                MMA_BF16(C[s][n], ah0,ah1,ah2,ah3, bh0[n], bh1[n]);  // hi*hi
                MMA_BF16(C[s][n], al0,al1,al2,al3, bh0[n], bh1[n]);  // lo*hi
                MMA_BF16(C[s][n], ah0,ah1,ah2,ah3, bl0[n], bl1[n]);  // hi*lo
            }
        }
    }
    // tap8 chunk: klow = ci(2t),ci(2t+1) tap8 ; khigh(t==0) = ci8,ci9 tap8
    {
        uint32_t bh0[2], bh1[2], bl0[2], bl1[2];
        #pragma unroll
        for (int n=0;n<2;n++){
            int bi = (n*8+g)*KPW + 40 + t;
            bh0[n]=ph[bi]; bh1[n]=ph[bi+4];
            bl0[n]=pl[bi]; bl1[n]=pl[bi+4];
        }
        const uint32_t* f8 = tile + w*TROWP + g + 3 + 2*TROWP + 2;
        #pragma unroll
        for (int s=0;s<2;s++){
            const uint32_t* fs = f8 + 16*s;
            uint32_t e0 = fs[(2*t)*TCI_STRIDE],   e1 = fs[(2*t+1)*TCI_STRIDE];
            uint32_t e2 = fs[(2*t)*TCI_STRIDE+8], e3 = fs[(2*t+1)*TCI_STRIDE+8];
            uint32_t ah0,al0,ah1,al1,ah2=0u,al2=0u,ah3=0u,al3=0u;
            PRMT(ah0, e0, e1, 0x7632); PRMT(al0, e0, e1, 0x5410);
            PRMT(ah1, e2, e3, 0x7632); PRMT(al1, e2, e3, 0x5410);
            if (t == 0){
                uint32_t r0 = fs[8*TCI_STRIDE],   r1 = fs[9*TCI_STRIDE];
                uint32_t r2 = fs[8*TCI_STRIDE+8], r3 = fs[9*TCI_STRIDE+8];
                PRMT(ah2, r0, r1, 0x7632); PRMT(al2, r0, r1, 0x5410);
                PRMT(ah3, r2, r3, 0x7632); PRMT(al3, r2, r3, 0x5410);
            }
            #pragma unroll
            for (int n=0;n<2;n++){
                MMA_BF16(C[s][n], ah0,ah1,ah2,ah3, bh0[n], bh1[n]);
                MMA_BF16(C[s][n], al0,al1,al2,al3, bh0[n], bh1[n]);
                MMA_BF16(C[s][n], ah0,ah1,ah2,ah3, bl0[n], bl1[n]);
            }
        }
    }
}

// dual: same A fragments feed two accumulator/panel sets (h tile shared)
__device__ __forceinline__ void conv_hmma_dual(
    float C1[2][2][4], float C2[2][2][4], const uint32_t* tile,
    const uint32_t* p1h, const uint32_t* p1l,
    const uint32_t* p2h, const uint32_t* p2l,
    int w, int g, int t, int off0, int off1)
{
    #pragma unroll 1
    for (int c=0; c<5; c++){
        uint32_t b1h0[2], b1h1[2], b1l0[2], b1l1[2];
        uint32_t b2h0[2], b2h1[2], b2l0[2], b2l1[2];
        #pragma unroll
        for (int n=0;n<2;n++){
            int bi = (n*8+g)*KPW + c*8 + t;
            b1h0[n]=p1h[bi]; b1h1[n]=p1h[bi+4];
            b1l0[n]=p1l[bi]; b1l1[n]=p1l[bi+4];
            b2h0[n]=p2h[bi]; b2h1[n]=p2h[bi+4];
            b2l0[n]=p2l[bi]; b2l1[n]=p2l[bi+4];
        }
        const uint32_t* fe = tile + (2*c)*TCI_STRIDE + w*TROWP + g + 3;
        #pragma unroll
        for (int s=0;s<2;s++){
            const uint32_t* fs = fe + 16*s;
            const uint32_t* fo = fs + TCI_STRIDE;
            uint32_t e0=fs[off0], e1=fs[off1], e2=fs[off0+8], e3=fs[off1+8];
            uint32_t q0=fo[off0], q1=fo[off1], q2=fo[off0+8], q3=fo[off1+8];
            uint32_t ah0,al0,ah1,al1,ah2,al2,ah3,al3;
            PRMT(ah0, e0, e1, 0x7632); PRMT(al0, e0, e1, 0x5410);
            PRMT(ah1, e2, e3, 0x7632); PRMT(al1, e2, e3, 0x5410);
            PRMT(ah2, q0, q1, 0x7632); PRMT(al2, q0, q1, 0x5410);
            PRMT(ah3, q2, q3, 0x7632); PRMT(al3, q2, q3, 0x5410);
            #pragma unroll
            for (int n=0;n<2;n++){
                MMA_BF16(C1[s][n], ah0,ah1,ah2,ah3, b1h0[n], b1h1[n]);
                MMA_BF16(C1[s][n], al0,al1,al2,al3, b1h0[n], b1h1[n]);
                MMA_BF16(C1[s][n], ah0,ah1,ah2,ah3, b1l0[n], b1l1[n]);
                MMA_BF16(C2[s][n], ah0,ah1,ah2,ah3, b2h0[n], b2h1[n]);
                MMA_BF16(C2[s][n], al0,al1,al2,al3, b2h0[n], b2h1[n]);
                MMA_BF16(C2[s][n], ah0,ah1,ah2,ah3, b2l0[n], b2l1[n]);
            }
        }
    }
    {
        uint32_t b1h0[2], b1h1[2], b1l0[2], b1l1[2];
        uint32_t b2h0[2], b2h1[2], b2l0[2], b2l1[2];
        #pragma unroll
        for (int n=0;n<2;n++){
            int bi = (n*8+g)*KPW + 40 + t;
            b1h0[n]=p1h[bi]; b1h1[n]=p1h[bi+4];
            b1l0[n]=p1l[bi]; b1l1[n]=p1l[bi+4];
            b2h0[n]=p2h[bi]; b2h1[n]=p2h[bi+4];
            b2l0[n]=p2l[bi]; b2l1[n]=p2l[bi+4];
        }
        const uint32_t* f8 = tile + w*TROWP + g + 3 + 2*TROWP + 2;
        #pragma unroll
        for (int s=0;s<2;s++){
            const uint32_t* fs = f8 + 16*s;
            uint32_t e0 = fs[(2*t)*TCI_STRIDE],   e1 = fs[(2*t+1)*TCI_STRIDE];
            uint32_t e2 = fs[(2*t)*TCI_STRIDE+8], e3 = fs[(2*t+1)*TCI_STRIDE+8];
            uint32_t ah0,al0,ah1,al1,ah2=0u,al2=0u,ah3=0u,al3=0u;
            PRMT(ah0, e0, e1, 0x7632); PRMT(al0, e0, e1, 0x5410);
            PRMT(ah1, e2, e3, 0x7632); PRMT(al1, e2, e3, 0x5410);
            if (t == 0){
                uint32_t r0 = fs[8*TCI_STRIDE],   r1 = fs[9*TCI_STRIDE];
                uint32_t r2 = fs[8*TCI_STRIDE+8], r3 = fs[9*TCI_STRIDE+8];
                PRMT(ah2, r0, r1, 0x7632); PRMT(al2, r0, r1, 0x5410);
                PRMT(ah3, r2, r3, 0x7632); PRMT(al3, r2, r3, 0x5410);
            }
            #pragma unroll
            for (int n=0;n<2;n++){
                MMA_BF16(C1[s][n], ah0,ah1,ah2,ah3, b1h0[n], b1h1[n]);
                MMA_BF16(C1[s][n], al0,al1,al2,al3, b1h0[n], b1h1[n]);
                MMA_BF16(C1[s][n], ah0,ah1,ah2,ah3, b1l0[n], b1l1[n]);
                MMA_BF16(C2[s][n], ah0,ah1,ah2,ah3, b2h0[n], b2h1[n]);
                MMA_BF16(C2[s][n], al0,al1,al2,al3, b2h0[n], b2h1[n]);
                MMA_BF16(C2[s][n], ah0,ah1,ah2,ah3, b2l0[n], b2l1[n]);
            }
        }
    }
}

// ================= Kernel 2: HMMA fused convs + GRU =================
__global__ __launch_bounds__(256,2) void k2_conv(
    const float* __restrict__ h_nodes,
    const float* __restrict__ g_decomp, const float* __restrict__ be_decomp,
    const float* __restrict__ g_cu, const float* __restrict__ be_cu,
    const float* __restrict__ g_cl, const float* __restrict__ be_cl,
    const float* __restrict__ wg_u, const float* __restrict__ bg_u,
    const float* __restrict__ wc_u, const float* __restrict__ g_u, const float* __restrict__ be_u,
    const float* __restrict__ wg_l, const float* __restrict__ bg_l,
    const float* __restrict__ wc_l, const float* __restrict__ g_l, const float* __restrict__ be_l,
    float* __restrict__ out_xh)
{
    extern __shared__ __align__(16) char smem[];
    float* s_par = (float*)(smem + SM_PAR);

    int z = blockIdx.z; int b = z >> 1; int half = z & 1;
    const float* gcv  = half ? g_cl  : g_cu;
    const float* becv = half ? be_cl : be_cu;
    const uint32_t* aX  = (half ? g_a2 : g_a1) + (size_t)b*CHW;
    const uint32_t* hpX = g_hp + (size_t)(half*NB + b)*CHW;
    const float* hX   = h_nodes + (size_t)((half?2:1)*NB + b)*CHW;
    const float* wgv  = half ? wg_l : wg_u;
    const float* bgv  = half ? bg_l : bg_u;
    const float* wcv  = half ? wc_l : wc_u;
    const float* ggv  = half ? g_l  : g_u;
    const float* bev  = half ? be_l : be_u;
    float* outp       = out_xh + (size_t)((half?2:1)*NB + b)*CHW;
    int nparts = half ? 2 : 4;
    int pidx0  = half ? 4 : 0;

    int tid = threadIdx.x;
    int w = tid >> 5, lane = tid & 31;
    int g = lane >> 2, t = lane & 3;
    int x0 = blockIdx.x*TILE_W, y0 = blockIdx.y*TILE_H;

    int tp0 = 2*t, tp1 = 2*t+1;
    int dy0 = tp0/3, dx0 = tp0 - 3*dy0;
    int dy1 = tp1/3, dx1 = tp1 - 3*dy1;
    int off0 = dy0*TROWP + dx0, off1 = dy1*TROWP + dx1;

    // ---- issue panel + a/h tile cp.async (one group) ----
    {
        unsigned sb = smem_to_u32(smem);
        #pragma unroll
        for (int j=0;j<7;j++){
            int i = tid + j*256;          // 8 panels x 208 chunks = 1664
            if (i < 8*PANEL_CHUNKS){
                int lp = i / PANEL_CHUNKS, within = i - lp*PANEL_CHUNKS;
                int gp = (lp < 4) ? lp : ((half ? 8 : 4) + (lp-4));
                const char* gsrc = (const char*)g_wp + (size_t)gp*PANEL_B + within*16;
                unsigned d = sb + (unsigned)(SM_PANELS + lp*PANEL_B + within*16);
                asm volatile("cp.async.cg.shared.global [%0], [%1], 16;" :: "r"(d), "l"(gsrc));
            }
        }
        stage_tile(smem, SM_T0, aX, tid, x0, y0);
        stage_tile(smem, SM_T1, hpX, tid, x0, y0);
        CP_COMMIT();
    }

    // ---- params ----
    if (tid < 10){
        s_par[P_GD+tid]=g_decomp[tid]; s_par[P_BED+tid]=be_decomp[tid];
        s_par[P_GC+tid]=gcv[tid];      s_par[P_BEC+tid]=becv[tid];
        s_par[P_GG+tid]=ggv[tid];      s_par[P_BEG+tid]=bev[tid];
    }
    if (tid >= 32 && tid < 72) s_par[P_WG + tid-32] = wgv[tid-32];
    if (tid == 72) { s_par[P_BG]=bgv[0]; s_par[P_BG+1]=bgv[1]; }
    if (tid < 100){ s_par[P_WC+tid] = wcv[tid]; s_par[P_WC+100+tid] = wcv[100+tid]; }

    CP_WAIT0();
    __syncthreads();

    // issue part0 -> T2
    stage_tile(smem, SM_T2, g_pm + (size_t)(pidx0*NB + b)*CHW, tid, x0, y0);
    CP_COMMIT();

    const uint32_t* pan = (const uint32_t*)(smem + SM_PANELS);
    const uint32_t* p_wdta_h = pan + 0*(PANEL_B/4);
    const uint32_t* p_wdta_l = pan + 1*(PANEL_B/4);
    const uint32_t* p_wdth_h = pan + 2*(PANEL_B/4);
    const uint32_t* p_wdth_l = pan + 3*(PANEL_B/4);
    const uint32_t* p_wcth_h = pan + 4*(PANEL_B/4);
    const uint32_t* p_wcth_l = pan + 5*(PANEL_B/4);
    const uint32_t* p_wctp_h = pan + 6*(PANEL_B/4);
    const uint32_t* p_wctp_l = pan + 7*(PANEL_B/4);

    int o0 = 2*t, o1 = 2*t+1, o8 = 8+2*t, o9 = 9+2*t;
    float gd_[4]  = { s_par[P_GD+o0],  s_par[P_GD+o1],  s_par[P_GD+o8],  s_par[P_GD+o9]  };
    float bed_[4] = { s_par[P_BED+o0], s_par[P_BED+o1], s_par[P_BED+o8], s_par[P_BED+o9] };
    float gc_[4]  = { s_par[P_GC+o0],  s_par[P_GC+o1],  s_par[P_GC+o8],  s_par[P_GC+o9]  };
    float bec_[4] = { s_par[P_BEC+o0], s_par[P_BEC+o1], s_par[P_BEC+o8], s_par[P_BEC+o9] };

    // ---- a-tile conv: Dd = wdt[:,0:10](x)a ----
    float Dd[2][2][4];
    #pragma unroll
    for (int s=0;s<2;s++)
        #pragma unroll
        for (int n=0;n<2;n++)
            #pragma unroll
            for (int j=0;j<4;j++) Dd[s][n][j] = 0.0f;
    conv_hmma(Dd, (const uint32_t*)(smem + SM_T0), p_wdta_h, p_wdta_l, w, g, t, off0, off1);

    // ---- h-tile dual conv ----
    float accA[2][2][4];
    #pragma unroll
    for (int s=0;s<2;s++)
        #pragma unroll
        for (int n=0;n<2;n++)
            #pragma unroll
            for (int j=0;j<4;j++) accA[s][n][j] = 0.0f;
    conv_hmma_dual(Dd, accA, (const uint32_t*)(smem + SM_T1),
                   p_wdth_h, p_wdth_l, p_wcth_h, p_wcth_l, w, g, t, off0, off1);

    #pragma unroll
    for (int s=0;s<2;s++)
        #pragma unroll
        for (int n=0;n<2;n++)
            #pragma unroll
            for (int j=0;j<4;j++){
                int oi = n*2 + (j&1);
                Dd[s][n][j] = fmaxf(fmaf(gd_[oi], Dd[s][n][j], bed_[oi]), 0.0f);
            }

    __syncthreads();   // all warps done reading T0/T1 before ring reuse

    // ---- part loop (ring T2,T0,T1) ----
    const int bufoff[3] = {SM_T2, SM_T0, SM_T1};
    for (int part=0; part<nparts; part++){
        if (part+1 < nparts){
            stage_tile(smem, bufoff[(part+1)%3], g_pm + (size_t)((pidx0+part+1)*NB + b)*CHW, tid, x0, y0);
            CP_COMMIT();
            CP_WAIT1();
        } else {
            CP_WAIT0();
        }
        __syncthreads();

        float Cp[2][2][4];
        #pragma unroll
        for (int s=0;s<2;s++)
            #pragma unroll
            for (int n=0;n<2;n++)
                #pragma unroll
                for (int j=0;j<4;j++) Cp[s][n][j] = accA[s][n][j];
        conv_hmma(Cp, (const uint32_t*)(smem + bufoff[part%3]), p_wctp_h, p_wctp_l, w, g, t, off0, off1);
        #pragma unroll
        for (int s=0;s<2;s++)
            #pragma unroll
            for (int n=0;n<2;n++)
                #pragma unroll
                for (int j=0;j<4;j++){
                    int oi = n*2 + (j&1);
                    Dd[s][n][j] += fmaxf(fmaf(gc_[oi], Cp[s][n][j], bec_[oi]), 0.0f);
                }
    }

    // ---- scatter msg fragments to smem (reuse T0) ----
    __syncthreads();
    float* s_msg = (float*)(smem + SM_T0);
    #pragma unroll
    for (int s=0;s<2;s++){
        int m0 = w*32 + s*16 + g;
        #pragma unroll
        for (int n=0;n<2;n++){
            if (n == 0 || t == 0){
                int oc = n*8 + 2*t;
                *(float2*)&s_msg[m0*12 + oc]     = make_float2(Dd[s][n][0], Dd[s][n][1]);
                *(float2*)&s_msg[(m0+8)*12 + oc] = make_float2(Dd[s][n][2], Dd[s][n][3]);
            }
        }
    }
    __syncthreads();

    // ---------- GRU epilogue (1 px per thread) ----------
    int py = y0 + (tid >> 5), pxx = x0 + (tid & 31);
    float msg[10], hcen[10];
    #pragma unroll
    for (int c=0;c<10;c++) msg[c] = s_msg[tid*12 + c];
    {
        const float* hc = hX + (size_t)py*NW + pxx;
        #pragma unroll
        for (int c=0;c<10;c++) hcen[c] = hc[(size_t)c*HW];
    }
    float g0 = s_par[P_BG], g1 = s_par[P_BG+1];
    #pragma unroll
    for (int c=0;c<10;c++){
        g0 = fmaf(s_par[P_WG+c],    msg[c],  g0);
        g0 = fmaf(s_par[P_WG+10+c], hcen[c], g0);
        g1 = fmaf(s_par[P_WG+20+c], msg[c],  g1);
        g1 = fmaf(s_par[P_WG+30+c], hcen[c], g1);
    }
    float rr = sigmoidf_(g0), uu = sigmoidf_(g1);
    float rh[10];
    #pragma unroll
    for (int c=0;c<10;c++) rh[c] = rr*hcen[c];

    float* op = outp + (size_t)py*NW + pxx;
    #pragma unroll
    for (int o=0;o<10;o++){
        float s = 0.0f;
        #pragma unroll
        for (int c=0;c<10;c++){
            s = fmaf(s_par[P_WC + o*20 + c],      msg[c], s);
            s = fmaf(s_par[P_WC + o*20 + 10 + c], rh[c],  s);
        }
        float cn = fmaf(s_par[P_GG+o], s, s_par[P_BEG+o]);
        cn = cn > 0.0f ? cn : 0.01f*cn;
        op[(size_t)o*HW] = (1.0f-uu)*hcen[o] + uu*cn;
    }
}

// ================= launcher =================
extern "C" void kernel_launch(void* const* d_in, const int* in_sizes, int n_in,
                              void* d_out, int out_size)
{
    const float* f_nodes  = (const float*)d_in[0];
    const float* h_nodes  = (const float*)d_in[1];
    const float* p_nodes  = (const float*)d_in[2];
    const float* w_dmap   = (const float*)d_in[4];
    const float* b_dmap   = (const float*)d_in[5];
    const float* w_decomp = (const float*)d_in[6];
    const float* g_decomp = (const float*)d_in[7];
    const float* be_decomp= (const float*)d_in[8];
    const float* w_cau    = (const float*)d_in[9];
    const float* b_cau    = (const float*)d_in[10];
    const float* w_cal    = (const float*)d_in[11];
    const float* b_cal    = (const float*)d_in[12];
    const float* w_cu     = (const float*)d_in[13];
    const float* g_cu     = (const float*)d_in[14];
    const float* be_cu    = (const float*)d_in[15];
    const float* w_cl     = (const float*)d_in[16];
    const float* g_cl     = (const float*)d_in[17];
    const float* be_cl    = (const float*)d_in[18];
    const float* wg_u     = (const float*)d_in[19];
    const float* bg_u     = (const float*)d_in[20];
    const float* wc_u     = (const float*)d_in[21];
    const float* g_u      = (const float*)d_in[22];
    const float* be_u     = (const float*)d_in[23];
    const float* wg_l     = (const float*)d_in[24];
    const float* bg_l     = (const float*)d_in[25];
    const float* wc_l     = (const float*)d_in[26];
    const float* g_l      = (const float*)d_in[27];
    const float* be_l     = (const float*)d_in[28];

    float* out        = (float*)d_out;
    float* out_decomp = out + (size_t)3*NB*CHW;
    float* out_cmu    = out_decomp + (size_t)NB*3*HW;
    float* out_cml    = out_cmu + (size_t)NB*HW;

    k1_pointwise<<<NB*HW/1024, 256>>>(f_nodes, h_nodes, p_nodes,
                                      w_dmap, b_dmap, w_cau, b_cau, w_cal, b_cal,
                                      w_decomp, w_cu, w_cl,
                                      out_decomp, out_cmu, out_cml, out);

    static int smem_set = 0;
    if (!smem_set){
        cudaFuncSetAttribute(k2_conv, cudaFuncAttributeMaxDynamicSharedMemorySize, SMEM_BYTES);
        smem_set = 1;
    }
    dim3 g2(NW/TILE_W, NH/TILE_H, 2*NB), b2(256, 1, 1);
    k2_conv<<<g2, b2, SMEM_BYTES>>>(h_nodes,
                                    g_decomp, be_decomp,
                                    g_cu, be_cu, g_cl, be_cl,
                                    wg_u, bg_u, wc_u, g_u, be_u,
                                    wg_l, bg_l, wc_l, g_l, be_l,
                                    out);
}

// round 16
// speedup vs baseline: 1.5379x; 1.0073x over previous
#include <cuda_runtime.h>
#include <cuda_bf16.h>
#include <cstdint>

#define NB 8
#define NC 10
#define NH 192
#define NW 192
#define HW (NH*NW)
#define CHW (NC*HW)

// ---------------- k2 geometry ----------------
#define TILE_W 32
#define TILE_H 8
#define TROWP 40              /* tile row words, base gx = x0-4 */
#define TROWS 10              /* 8 + 2 halo */
#define TCI_STRIDE 404        /* TROWS*TROWP + 4 pad: 404 % 32 = 20 -> tap8 loads conflict-free */
#define TILE_B 16160          /* 10ch * 404 * 4 bytes */
#define TILE_CHUNKS 1000      /* 16B chunks per 10-ch tile */

// weight panels: [16 outs x 96 K] bf16, row stride 52 words (104 shorts), conflict-free
#define KPW 52
#define PANEL_SH 1664         /* 16*104 shorts */
#define PANEL_B 3328          /* bytes */
#define PANEL_CHUNKS 208      /* 16B chunks */

// smem byte layout
#define SM_PANELS 0           /* 8 local panels = 26624 */
#define SM_T0 26624
#define SM_T1 (SM_T0 + TILE_B)
#define SM_T2 (SM_T1 + TILE_B)
#define SM_PAR (SM_T2 + TILE_B)
#define SMEM_BYTES (SM_PAR + 1216)

// param offsets (floats)
#define P_GD 0
#define P_BED 10
#define P_GC 20
#define P_BEC 30
#define P_GG 40
#define P_BEG 50
#define P_WG 60
#define P_BG 100
#define P_WC 102

// ---------------- scratch (static device globals; no allocation) ----------------
// packed (hi<<16)|lo bf16 words
__device__ __align__(16) uint32_t g_a1[NB*CHW];
__device__ __align__(16) uint32_t g_a2[NB*CHW];
__device__ __align__(16) uint32_t g_pm[6*NB*CHW];
__device__ __align__(16) uint32_t g_hp[2*NB*CHW];
// 12 global panels: s=0..5 {wdt0,wdt1,wcu0,wcu1,wcl0,wcl1} x {hi,lo}
__device__ __align__(16) unsigned short g_wp[12*PANEL_SH];

__device__ __forceinline__ float sigmoidf_(float x){ return 1.0f/(1.0f+expf(-x)); }
__device__ __forceinline__ float4 f4fma(float s, float4 v, float4 a){
    return make_float4(fmaf(s,v.x,a.x), fmaf(s,v.y,a.y), fmaf(s,v.z,a.z), fmaf(s,v.w,a.w));
}
__device__ __forceinline__ float4 f4s(float s){ return make_float4(s,s,s,s); }

__device__ __forceinline__ uint32_t smem_to_u32(const void* p) {
    uint32_t a;
    asm("{ .reg .u64 t; cvta.to.shared.u64 t, %1; cvt.u32.u64 %0, t; }" : "=r"(a) : "l"(p));
    return a;
}
#define CP_COMMIT() asm volatile("cp.async.commit_group;")
#define CP_WAIT0()  asm volatile("cp.async.wait_group 0;" ::: "memory")
#define CP_WAIT1()  asm volatile("cp.async.wait_group 1;" ::: "memory")

// pack fp32 -> (truncated-bf16 hi << 16) | rn-bf16(residual)
__device__ __forceinline__ uint32_t packw(float x){
    uint32_t u = __float_as_uint(x);
    float lof = x - __uint_as_float(u & 0xffff0000u);
    __nv_bfloat16 lb = __float2bfloat16(lof);
    unsigned short ls = *(unsigned short*)&lb;
    return (u & 0xffff0000u) | (uint32_t)ls;
}
__device__ __forceinline__ uint4 packw4(float4 v){
    uint4 r;
    r.x = packw(v.x); r.y = packw(v.y); r.z = packw(v.z); r.w = packw(v.w);
    return r;
}

// ================= Kernel 1: pointwise + packing + panel prep + slot0 =================
__global__ __launch_bounds__(256) void k1_pointwise(
    const float* __restrict__ f_nodes,
    const float* __restrict__ h_nodes,
    const float* __restrict__ p_nodes,
    const float* __restrict__ w_dmap, const float* __restrict__ b_dmap,
    const float* __restrict__ w_cau,  const float* __restrict__ b_cau,
    const float* __restrict__ w_cal,  const float* __restrict__ b_cal,
    const float* __restrict__ w_decomp, const float* __restrict__ w_cu, const float* __restrict__ w_cl,
    float* __restrict__ out_decomp, float* __restrict__ out_cmu, float* __restrict__ out_cml,
    float* __restrict__ out_xh)
{
    // ---- blocks 0..5: weight panel prep (K=96 compact layout) ----
    if (blockIdx.x < 6){
        int s = blockIdx.x;
        const float* w = (s < 2) ? w_decomp : ((s < 4) ? w_cu : w_cl);
        int cibase = (s & 1) * 10;
        for (int i = threadIdx.x; i < PANEL_SH; i += 256){
            int n = i / 104, kk = i - n*104;
            float val = 0.0f;
            if (n < 10 && kk < 96){
                int c = kk >> 4, j = kk & 15;
                int ci = -1, tap = 0;
                if (c < 5){ ci = 2*c + (j >> 3); tap = j & 7; }
                else if (j < 10){ ci = j; tap = 8; }
                if (ci >= 0) val = w[(n*20 + cibase + ci)*9 + tap];
            }
            unsigned u = __float_as_uint(val);
            unsigned short hb = (unsigned short)(u >> 16);
            float lof = val - __uint_as_float(u & 0xffff0000u);
            __nv_bfloat16 lb = __float2bfloat16(lof);
            g_wp[(size_t)(2*s)*PANEL_SH + i]   = hb;
            g_wp[(size_t)(2*s+1)*PANEL_SH + i] = *(unsigned short*)&lb;
        }
    }

    __shared__ float s_wd[90], s_bd[3], s_wcau[40], s_wcal[20], s_bc[2];
    int t = threadIdx.x;
    if (t < 90)              s_wd[t]        = w_dmap[t];
    if (t >= 96 && t < 99)   s_bd[t-96]     = b_dmap[t-96];
    if (t >= 128 && t < 168) s_wcau[t-128]  = w_cau[t-128];
    if (t >= 192 && t < 212) s_wcal[t-192]  = w_cal[t-192];
    if (t == 224) s_bc[0] = b_cau[0];
    if (t == 225) s_bc[1] = b_cal[0];
    __syncthreads();

    int pix = (blockIdx.x*256 + t)*4;
    int b = pix / HW, p = pix - b*HW;

    const float* f1b = f_nodes + (size_t)(1*NB + b)*CHW + p;
    const float* h1b = h_nodes + (size_t)(1*NB + b)*CHW + p;
    const float* h2b = h_nodes + (size_t)(2*NB + b)*CHW + p;

    uint32_t* hp1 = g_hp + (size_t)(0*NB + b)*CHW + p;
    uint32_t* hp2 = g_hp + (size_t)(1*NB + b)*CHW + p;

    float4 f[10];
    float4 dm0 = f4s(s_bd[0]), dm1 = f4s(s_bd[1]), dm2 = f4s(s_bd[2]);
    #pragma unroll
    for (int c=0;c<10;c++){
        f[c]       = *(const float4*)(f1b + c*HW);
        float4 u1  = *(const float4*)(h1b + c*HW);
        float4 u2  = *(const float4*)(h2b + c*HW);
        *(uint4*)(hp1 + c*HW) = packw4(u1);
        *(uint4*)(hp2 + c*HW) = packw4(u2);
        dm0 = f4fma(s_wd[ 0+c],f[c],dm0); dm0 = f4fma(s_wd[10+c],u1,dm0); dm0 = f4fma(s_wd[20+c],u2,dm0);
        dm1 = f4fma(s_wd[30+c],f[c],dm1); dm1 = f4fma(s_wd[40+c],u1,dm1); dm1 = f4fma(s_wd[50+c],u2,dm1);
        dm2 = f4fma(s_wd[60+c],f[c],dm2); dm2 = f4fma(s_wd[70+c],u1,dm2); dm2 = f4fma(s_wd[80+c],u2,dm2);
    }

    float4 att1, att2;
    {
        float d0v[4] = {dm0.x,dm0.y,dm0.z,dm0.w};
        float d1v[4] = {dm1.x,dm1.y,dm1.z,dm1.w};
        float d2v[4] = {dm2.x,dm2.y,dm2.z,dm2.w};
        float a1v[4], a2v[4];
        #pragma unroll
        for (int i=0;i<4;i++){
            float mx = fmaxf(d0v[i], fmaxf(d1v[i], d2v[i]));
            float e0 = expf(d0v[i]-mx), e1 = expf(d1v[i]-mx), e2 = expf(d2v[i]-mx);
            float inv = 1.0f/(e0+e1+e2);
            a1v[i] = e1*inv; a2v[i] = e2*inv;
        }
        att1 = make_float4(a1v[0],a1v[1],a1v[2],a1v[3]);
        att2 = make_float4(a2v[0],a2v[1],a2v[2],a2v[3]);
    }

    uint32_t* a1p = g_a1 + (size_t)b*CHW + p;
    uint32_t* a2p = g_a2 + (size_t)b*CHW + p;
    #pragma unroll
    for (int c=0;c<10;c++){
        *(uint4*)(a1p + c*HW) = packw4(make_float4(f[c].x*att1.x, f[c].y*att1.y, f[c].z*att1.z, f[c].w*att1.w));
        *(uint4*)(a2p + c*HW) = packw4(make_float4(f[c].x*att2.x, f[c].y*att2.y, f[c].z*att2.z, f[c].w*att2.w));
    }

    *(float4*)(out_decomp + (size_t)(b*3+0)*HW + p) = dm0;
    *(float4*)(out_decomp + (size_t)(b*3+1)*HW + p) = dm1;
    *(float4*)(out_decomp + (size_t)(b*3+2)*HW + p) = dm2;

    float4 su = f4s(s_bc[0]);
    #pragma unroll
    for (int j=0;j<4;j++){
        const float* pp = p_nodes + (size_t)((j+1)*NB + b)*CHW + p;
        #pragma unroll
        for (int c=0;c<10;c++) su = f4fma(s_wcau[j*10+c], *(const float4*)(pp + c*HW), su);
    }
    float4 mu = make_float4(sigmoidf_(su.x), sigmoidf_(su.y), sigmoidf_(su.z), sigmoidf_(su.w));
    *(float4*)(out_cmu + (size_t)b*HW + p) = mu;

    float4 sl = f4s(s_bc[1]);
    #pragma unroll
    for (int j=0;j<2;j++){
        const float* pp = p_nodes + (size_t)((j+5)*NB + b)*CHW + p;
        #pragma unroll
        for (int c=0;c<10;c++) sl = f4fma(s_wcal[j*10+c], *(const float4*)(pp + c*HW), sl);
    }
    float4 ml = make_float4(sigmoidf_(sl.x), sigmoidf_(sl.y), sigmoidf_(sl.z), sigmoidf_(sl.w));
    *(float4*)(out_cml + (size_t)b*HW + p) = ml;

    #pragma unroll
    for (int j=0;j<4;j++){
        const float* pp = p_nodes + (size_t)((j+1)*NB + b)*CHW + p;
        uint32_t* od = g_pm + (size_t)(j*NB + b)*CHW + p;
        #pragma unroll
        for (int c=0;c<10;c++){
            float4 v = *(const float4*)(pp + c*HW);
            *(uint4*)(od + c*HW) = packw4(make_float4(v.x*mu.x, v.y*mu.y, v.z*mu.z, v.w*mu.w));
        }
    }
    #pragma unroll
    for (int j=0;j<2;j++){
        const float* pp = p_nodes + (size_t)((j+5)*NB + b)*CHW + p;
        uint32_t* od = g_pm + (size_t)((4+j)*NB + b)*CHW + p;
        #pragma unroll
        for (int c=0;c<10;c++){
            float4 v = *(const float4*)(pp + c*HW);
            *(uint4*)(od + c*HW) = packw4(make_float4(v.x*ml.x, v.y*ml.y, v.z*ml.z, v.w*ml.w));
        }
    }

    const float* h0 = h_nodes + (size_t)b*CHW + p;
    float* o0 = out_xh + (size_t)b*CHW + p;
    #pragma unroll
    for (int c=0;c<10;c++) *(float4*)(o0 + c*HW) = *(const float4*)(h0 + c*HW);
}

// ================= Kernel 2 helpers =================
__device__ __forceinline__ void stage_tile(char* smembase, int toff, const uint32_t* __restrict__ src,
                                           int tid, int x0, int y0)
{
    unsigned sbase = smem_to_u32(smembase + toff);
    #pragma unroll
    for (int j=0;j<4;j++){
        int i = tid + j*256;
        if (i < TILE_CHUNKS){
            int ci = i/100, rem = i - ci*100;
            int r = rem/10, c4 = rem - r*10;
            int gy = y0-1+r, gx = x0-4+c4*4;
            bool in = (gy>=0) & (gy<NH) & (gx>=0) & (gx<NW);
            const uint32_t* g = src + (size_t)ci*HW + (in ? (gy*NW+gx) : 0);
            unsigned d = sbase + (unsigned)((ci*TCI_STRIDE + r*TROWP + c4*4)*4);
            int ssz = in ? 16 : 0;
            asm volatile("cp.async.cg.shared.global [%0], [%1], 16, %2;" :: "r"(d), "l"(g), "r"(ssz));
        }
    }
}

#define PRMT(d, a, b, m) asm("prmt.b32 %0, %1, %2, %3;" : "=r"(d) : "r"(a), "r"(b), "n"(m))

#define MMA_BF16(c, a0,a1,a2,a3, b0,b1) \
    asm volatile("mma.sync.aligned.m16n8k16.row.col.f32.bf16.bf16.f32 " \
        "{%0,%1,%2,%3}, {%4,%5,%6,%7}, {%8,%9}, {%0,%1,%2,%3};" \
        : "+f"((c)[0]), "+f"((c)[1]), "+f"((c)[2]), "+f"((c)[3]) \
        : "r"(a0), "r"(a1), "r"(a2), "r"(a3), "r"(b0), "r"(b1))

// one conv: K=96 compact layout (5 even/odd-ci chunks + 1 tap8 chunk), 3-term split
__device__ __forceinline__ void conv_hmma(
    float C[2][2][4], const uint32_t* tile,
    const uint32_t* ph, const uint32_t* pl,
    int w, int g, int t, int off0, int off1)
{
    #pragma unroll 1
    for (int c=0; c<5; c++){
        uint32_t bh0[2], bh1[2], bl0[2], bl1[2];
        #pragma unroll
        for (int n=0;n<2;n++){
            int bi = (n*8+g)*KPW + c*8 + t;
            bh0[n]=ph[bi]; bh1[n]=ph[bi+4];
            bl0[n]=pl[bi]; bl1[n]=pl[bi+4];
        }
        const uint32_t* fe = tile + (2*c)*TCI_STRIDE + w*TROWP + g + 3;
        #pragma unroll
        for (int s=0;s<2;s++){
            const uint32_t* fs = fe + 16*s;
            const uint32_t* fo = fs + TCI_STRIDE;
            uint32_t e0=fs[off0], e1=fs[off1], e2=fs[off0+8], e3=fs[off1+8];
            uint32_t q0=fo[off0], q1=fo[off1], q2=fo[off0+8], q3=fo[off1+8];
            uint32_t ah0,al0,ah1,al1,ah2,al2,ah3,al3;
            PRMT(ah0, e0, e1, 0x7632); PRMT(al0, e0, e1, 0x5410);
            PRMT(ah1, e2, e3, 0x7632); PRMT(al1, e2, e3, 0x5410);
            PRMT(ah2, q0, q1, 0x7632); PRMT(al2, q0, q1, 0x5410);
            PRMT(ah3, q2, q3, 0x7632); PRMT(al3, q2, q3, 0x5410);
            #pragma unroll
            for (int n=0;n<2;n++){
                MMA_BF16(C[s][n], ah0,ah1,ah2,ah3, bh0[n], bh1[n]);  // hi*hi
                MMA_BF16(C[s][n], al0,al1,al2,al3, bh0[n], bh1[n]);  // lo*hi
                MMA_BF16(C[s][n], ah0,ah1,ah2,ah3, bl0[n], bl1[n]);  // hi*lo
            }
        }
    }
    // tap8 chunk: klow = ci(2t),ci(2t+1) tap8 ; khigh(t==0) = ci8,ci9 tap8
    {
        uint32_t bh0[2], bh1[2], bl0[2], bl1[2];
        #pragma unroll
        for (int n=0;n<2;n++){
            int bi = (n*8+g)*KPW + 40 + t;
            bh0[n]=ph[bi]; bh1[n]=ph[bi+4];
            bl0[n]=pl[bi]; bl1[n]=pl[bi+4];
        }
        const uint32_t* f8 = tile + w*TROWP + g + 3 + 2*TROWP + 2;
        #pragma unroll
        for (int s=0;s<2;s++){
            const uint32_t* fs = f8 + 16*s;
            uint32_t e0 = fs[(2*t)*TCI_STRIDE],   e1 = fs[(2*t+1)*TCI_STRIDE];
            uint32_t e2 = fs[(2*t)*TCI_STRIDE+8], e3 = fs[(2*t+1)*TCI_STRIDE+8];
            uint32_t ah0,al0,ah1,al1,ah2=0u,al2=0u,ah3=0u,al3=0u;
            PRMT(ah0, e0, e1, 0x7632); PRMT(al0, e0, e1, 0x5410);
            PRMT(ah1, e2, e3, 0x7632); PRMT(al1, e2, e3, 0x5410);
            if (t == 0){
                uint32_t r0 = fs[8*TCI_STRIDE],   r1 = fs[9*TCI_STRIDE];
                uint32_t r2 = fs[8*TCI_STRIDE+8], r3 = fs[9*TCI_STRIDE+8];
                PRMT(ah2, r0, r1, 0x7632); PRMT(al2, r0, r1, 0x5410);
                PRMT(ah3, r2, r3, 0x7632); PRMT(al3, r2, r3, 0x5410);
            }
            #pragma unroll
            for (int n=0;n<2;n++){
                MMA_BF16(C[s][n], ah0,ah1,ah2,ah3, bh0[n], bh1[n]);
                MMA_BF16(C[s][n], al0,al1,al2,al3, bh0[n], bh1[n]);
                MMA_BF16(C[s][n], ah0,ah1,ah2,ah3, bl0[n], bl1[n]);
            }
        }
    }
}

// dual: same A fragments feed two accumulator/panel sets (h tile shared)
__device__ __forceinline__ void conv_hmma_dual(
    float C1[2][2][4], float C2[2][2][4], const uint32_t* tile,
    const uint32_t* p1h, const uint32_t* p1l,
    const uint32_t* p2h, const uint32_t* p2l,
    int w, int g, int t, int off0, int off1)
{
    #pragma unroll 1
    for (int c=0; c<5; c++){
        uint32_t b1h0[2], b1h1[2], b1l0[2], b1l1[2];
        uint32_t b2h0[2], b2h1[2], b2l0[2], b2l1[2];
        #pragma unroll
        for (int n=0;n<2;n++){
            int bi = (n*8+g)*KPW + c*8 + t;
            b1h0[n]=p1h[bi]; b1h1[n]=p1h[bi+4];
            b1l0[n]=p1l[bi]; b1l1[n]=p1l[bi+4];
            b2h0[n]=p2h[bi]; b2h1[n]=p2h[bi+4];
            b2l0[n]=p2l[bi]; b2l1[n]=p2l[bi+4];
        }
        const uint32_t* fe = tile + (2*c)*TCI_STRIDE + w*TROWP + g + 3;
        #pragma unroll
        for (int s=0;s<2;s++){
            const uint32_t* fs = fe + 16*s;
            const uint32_t* fo = fs + TCI_STRIDE;
            uint32_t e0=fs[off0], e1=fs[off1], e2=fs[off0+8], e3=fs[off1+8];
            uint32_t q0=fo[off0], q1=fo[off1], q2=fo[off0+8], q3=fo[off1+8];
            uint32_t ah0,al0,ah1,al1,ah2,al2,ah3,al3;
            PRMT(ah0, e0, e1, 0x7632); PRMT(al0, e0, e1, 0x5410);
            PRMT(ah1, e2, e3, 0x7632); PRMT(al1, e2, e3, 0x5410);
            PRMT(ah2, q0, q1, 0x7632); PRMT(al2, q0, q1, 0x5410);
            PRMT(ah3, q2, q3, 0x7632); PRMT(al3, q2, q3, 0x5410);
            #pragma unroll
            for (int n=0;n<2;n++){
                MMA_BF16(C1[s][n], ah0,ah1,ah2,ah3, b1h0[n], b1h1[n]);
                MMA_BF16(C1[s][n], al0,al1,al2,al3, b1h0[n], b1h1[n]);
                MMA_BF16(C1[s][n], ah0,ah1,ah2,ah3, b1l0[n], b1l1[n]);
                MMA_BF16(C2[s][n], ah0,ah1,ah2,ah3, b2h0[n], b2h1[n]);
                MMA_BF16(C2[s][n], al0,al1,al2,al3, b2h0[n], b2h1[n]);
                MMA_BF16(C2[s][n], ah0,ah1,ah2,ah3, b2l0[n], b2l1[n]);
            }
        }
    }
    {
        uint32_t b1h0[2], b1h1[2], b1l0[2], b1l1[2];
        uint32_t b2h0[2], b2h1[2], b2l0[2], b2l1[2];
        #pragma unroll
        for (int n=0;n<2;n++){
            int bi = (n*8+g)*KPW + 40 + t;
            b1h0[n]=p1h[bi]; b1h1[n]=p1h[bi+4];
            b1l0[n]=p1l[bi]; b1l1[n]=p1l[bi+4];
            b2h0[n]=p2h[bi]; b2h1[n]=p2h[bi+4];
            b2l0[n]=p2l[bi]; b2l1[n]=p2l[bi+4];
        }
        const uint32_t* f8 = tile + w*TROWP + g + 3 + 2*TROWP + 2;
        #pragma unroll
        for (int s=0;s<2;s++){
            const uint32_t* fs = f8 + 16*s;
            uint32_t e0 = fs[(2*t)*TCI_STRIDE],   e1 = fs[(2*t+1)*TCI_STRIDE];
            uint32_t e2 = fs[(2*t)*TCI_STRIDE+8], e3 = fs[(2*t+1)*TCI_STRIDE+8];
            uint32_t ah0,al0,ah1,al1,ah2=0u,al2=0u,ah3=0u,al3=0u;
            PRMT(ah0, e0, e1, 0x7632); PRMT(al0, e0, e1, 0x5410);
            PRMT(ah1, e2, e3, 0x7632); PRMT(al1, e2, e3, 0x5410);
            if (t == 0){
                uint32_t r0 = fs[8*TCI_STRIDE],   r1 = fs[9*TCI_STRIDE];
                uint32_t r2 = fs[8*TCI_STRIDE+8], r3 = fs[9*TCI_STRIDE+8];
                PRMT(ah2, r0, r1, 0x7632); PRMT(al2, r0, r1, 0x5410);
                PRMT(ah3, r2, r3, 0x7632); PRMT(al3, r2, r3, 0x5410);
            }
            #pragma unroll
            for (int n=0;n<2;n++){
                MMA_BF16(C1[s][n], ah0,ah1,ah2,ah3, b1h0[n], b1h1[n]);
                MMA_BF16(C1[s][n], al0,al1,al2,al3, b1h0[n], b1h1[n]);
                MMA_BF16(C1[s][n], ah0,ah1,ah2,ah3, b1l0[n], b1l1[n]);
                MMA_BF16(C2[s][n], ah0,ah1,ah2,ah3, b2h0[n], b2h1[n]);
                MMA_BF16(C2[s][n], al0,al1,al2,al3, b2h0[n], b2h1[n]);
                MMA_BF16(C2[s][n], ah0,ah1,ah2,ah3, b2l0[n], b2l1[n]);
            }
        }
    }
}

// ================= Kernel 2: HMMA fused convs + GRU =================
__global__ __launch_bounds__(256,2) void k2_conv(
    const float* __restrict__ h_nodes,
    const float* __restrict__ g_decomp, const float* __restrict__ be_decomp,
    const float* __restrict__ g_cu, const float* __restrict__ be_cu,
    const float* __restrict__ g_cl, const float* __restrict__ be_cl,
    const float* __restrict__ wg_u, const float* __restrict__ bg_u,
    const float* __restrict__ wc_u, const float* __restrict__ g_u, const float* __restrict__ be_u,
    const float* __restrict__ wg_l, const float* __restrict__ bg_l,
    const float* __restrict__ wc_l, const float* __restrict__ g_l, const float* __restrict__ be_l,
    float* __restrict__ out_xh)
{
    extern __shared__ __align__(16) char smem[];
    float* s_par = (float*)(smem + SM_PAR);

    int z = blockIdx.z; int b = z >> 1; int half = z & 1;
    const float* gcv  = half ? g_cl  : g_cu;
    const float* becv = half ? be_cl : be_cu;
    const uint32_t* aX  = (half ? g_a2 : g_a1) + (size_t)b*CHW;
    const uint32_t* hpX = g_hp + (size_t)(half*NB + b)*CHW;
    const float* hX   = h_nodes + (size_t)((half?2:1)*NB + b)*CHW;
    const float* wgv  = half ? wg_l : wg_u;
    const float* bgv  = half ? bg_l : bg_u;
    const float* wcv  = half ? wc_l : wc_u;
    const float* ggv  = half ? g_l  : g_u;
    const float* bev  = half ? be_l : be_u;
    float* outp       = out_xh + (size_t)((half?2:1)*NB + b)*CHW;
    int nparts = half ? 2 : 4;
    int pidx0  = half ? 4 : 0;

    int tid = threadIdx.x;
    int w = tid >> 5, lane = tid & 31;
    int g = lane >> 2, t = lane & 3;
    int x0 = blockIdx.x*TILE_W, y0 = blockIdx.y*TILE_H;

    int tp0 = 2*t, tp1 = 2*t+1;
    int dy0 = tp0/3, dx0 = tp0 - 3*dy0;
    int dy1 = tp1/3, dx1 = tp1 - 3*dy1;
    int off0 = dy0*TROWP + dx0, off1 = dy1*TROWP + dx1;

    // ---- issue panel + a/h tile cp.async (one group) ----
    {
        unsigned sb = smem_to_u32(smem);
        #pragma unroll
        for (int j=0;j<7;j++){
            int i = tid + j*256;          // 8 panels x 208 chunks = 1664
            if (i < 8*PANEL_CHUNKS){
                int lp = i / PANEL_CHUNKS, within = i - lp*PANEL_CHUNKS;
                int gp = (lp < 4) ? lp : ((half ? 8 : 4) + (lp-4));
                const char* gsrc = (const char*)g_wp + (size_t)gp*PANEL_B + within*16;
                unsigned d = sb + (unsigned)(SM_PANELS + lp*PANEL_B + within*16);
                asm volatile("cp.async.cg.shared.global [%0], [%1], 16;" :: "r"(d), "l"(gsrc));
            }
        }
        stage_tile(smem, SM_T0, aX, tid, x0, y0);
        stage_tile(smem, SM_T1, hpX, tid, x0, y0);
        CP_COMMIT();
    }

    // ---- params ----
    if (tid < 10){
        s_par[P_GD+tid]=g_decomp[tid]; s_par[P_BED+tid]=be_decomp[tid];
        s_par[P_GC+tid]=gcv[tid];      s_par[P_BEC+tid]=becv[tid];
        s_par[P_GG+tid]=ggv[tid];      s_par[P_BEG+tid]=bev[tid];
    }
    if (tid >= 32 && tid < 72) s_par[P_WG + tid-32] = wgv[tid-32];
    if (tid == 72) { s_par[P_BG]=bgv[0]; s_par[P_BG+1]=bgv[1]; }
    if (tid < 100){ s_par[P_WC+tid] = wcv[tid]; s_par[P_WC+100+tid] = wcv[100+tid]; }

    CP_WAIT0();
    __syncthreads();

    // issue part0 -> T2
    stage_tile(smem, SM_T2, g_pm + (size_t)(pidx0*NB + b)*CHW, tid, x0, y0);
    CP_COMMIT();

    const uint32_t* pan = (const uint32_t*)(smem + SM_PANELS);
    const uint32_t* p_wdta_h = pan + 0*(PANEL_B/4);
    const uint32_t* p_wdta_l = pan + 1*(PANEL_B/4);
    const uint32_t* p_wdth_h = pan + 2*(PANEL_B/4);
    const uint32_t* p_wdth_l = pan + 3*(PANEL_B/4);
    const uint32_t* p_wcth_h = pan + 4*(PANEL_B/4);
    const uint32_t* p_wcth_l = pan + 5*(PANEL_B/4);
    const uint32_t* p_wctp_h = pan + 6*(PANEL_B/4);
    const uint32_t* p_wctp_l = pan + 7*(PANEL_B/4);

    int o0 = 2*t, o1 = 2*t+1, o8 = 8+2*t, o9 = 9+2*t;
    float gd_[4]  = { s_par[P_GD+o0],  s_par[P_GD+o1],  s_par[P_GD+o8],  s_par[P_GD+o9]  };
    float bed_[4] = { s_par[P_BED+o0], s_par[P_BED+o1], s_par[P_BED+o8], s_par[P_BED+o9] };
    float gc_[4]  = { s_par[P_GC+o0],  s_par[P_GC+o1],  s_par[P_GC+o8],  s_par[P_GC+o9]  };
    float bec_[4] = { s_par[P_BEC+o0], s_par[P_BEC+o1], s_par[P_BEC+o8], s_par[P_BEC+o9] };

    // ---- a-tile conv: Dd = wdt[:,0:10](x)a ----
    float Dd[2][2][4];
    #pragma unroll
    for (int s=0;s<2;s++)
        #pragma unroll
        for (int n=0;n<2;n++)
            #pragma unroll
            for (int j=0;j<4;j++) Dd[s][n][j] = 0.0f;
    conv_hmma(Dd, (const uint32_t*)(smem + SM_T0), p_wdta_h, p_wdta_l, w, g, t, off0, off1);

    // ---- h-tile dual conv ----
    float accA[2][2][4];
    #pragma unroll
    for (int s=0;s<2;s++)
        #pragma unroll
        for (int n=0;n<2;n++)
            #pragma unroll
            for (int j=0;j<4;j++) accA[s][n][j] = 0.0f;
    conv_hmma_dual(Dd, accA, (const uint32_t*)(smem + SM_T1),
                   p_wdth_h, p_wdth_l, p_wcth_h, p_wcth_l, w, g, t, off0, off1);

    #pragma unroll
    for (int s=0;s<2;s++)
        #pragma unroll
        for (int n=0;n<2;n++)
            #pragma unroll
            for (int j=0;j<4;j++){
                int oi = n*2 + (j&1);
                Dd[s][n][j] = fmaxf(fmaf(gd_[oi], Dd[s][n][j], bed_[oi]), 0.0f);
            }

    __syncthreads();   // all warps done reading T0/T1 before ring reuse

    // ---- part loop (ring T2,T0,T1) ----
    const int bufoff[3] = {SM_T2, SM_T0, SM_T1};
    for (int part=0; part<nparts; part++){
        if (part+1 < nparts){
            stage_tile(smem, bufoff[(part+1)%3], g_pm + (size_t)((pidx0+part+1)*NB + b)*CHW, tid, x0, y0);
            CP_COMMIT();
            CP_WAIT1();
        } else {
            CP_WAIT0();
        }
        __syncthreads();

        float Cp[2][2][4];
        #pragma unroll
        for (int s=0;s<2;s++)
            #pragma unroll
            for (int n=0;n<2;n++)
                #pragma unroll
                for (int j=0;j<4;j++) Cp[s][n][j] = accA[s][n][j];
        conv_hmma(Cp, (const uint32_t*)(smem + bufoff[part%3]), p_wctp_h, p_wctp_l, w, g, t, off0, off1);
        #pragma unroll
        for (int s=0;s<2;s++)
            #pragma unroll
            for (int n=0;n<2;n++)
                #pragma unroll
                for (int j=0;j<4;j++){
                    int oi = n*2 + (j&1);
                    Dd[s][n][j] += fmaxf(fmaf(gc_[oi], Cp[s][n][j], bec_[oi]), 0.0f);
                }
    }

    // ---- scatter msg fragments to smem (reuse T0) ----
    __syncthreads();
    float* s_msg = (float*)(smem + SM_T0);
    #pragma unroll
    for (int s=0;s<2;s++){
        int m0 = w*32 + s*16 + g;
        #pragma unroll
        for (int n=0;n<2;n++){
            if (n == 0 || t == 0){
                int oc = n*8 + 2*t;
                *(float2*)&s_msg[m0*12 + oc]     = make_float2(Dd[s][n][0], Dd[s][n][1]);
                *(float2*)&s_msg[(m0+8)*12 + oc] = make_float2(Dd[s][n][2], Dd[s][n][3]);
            }
        }
    }
    __syncthreads();

    // ---------- GRU epilogue (1 px per thread) ----------
    int py = y0 + (tid >> 5), pxx = x0 + (tid & 31);
    float msg[10], hcen[10];
    #pragma unroll
    for (int c=0;c<10;c++) msg[c] = s_msg[tid*12 + c];
    {
        const float* hc = hX + (size_t)py*NW + pxx;
        #pragma unroll
        for (int c=0;c<10;c++) hcen[c] = hc[(size_t)c*HW];
    }
    float g0 = s_par[P_BG], g1 = s_par[P_BG+1];
    #pragma unroll
    for (int c=0;c<10;c++){
        g0 = fmaf(s_par[P_WG+c],    msg[c],  g0);
        g0 = fmaf(s_par[P_WG+10+c], hcen[c], g0);
        g1 = fmaf(s_par[P_WG+20+c], msg[c],  g1);
        g1 = fmaf(s_par[P_WG+30+c], hcen[c], g1);
    }
    float rr = sigmoidf_(g0), uu = sigmoidf_(g1);
    float rh[10];
    #pragma unroll
    for (int c=0;c<10;c++) rh[c] = rr*hcen[c];

    float* op = outp + (size_t)py*NW + pxx;
    #pragma unroll
    for (int o=0;o<10;o++){
        float s = 0.0f;
        #pragma unroll
        for (int c=0;c<10;c++){
            s = fmaf(s_par[P_WC + o*20 + c],      msg[c], s);
            s = fmaf(s_par[P_WC + o*20 + 10 + c], rh[c],  s);
        }
        float cn = fmaf(s_par[P_GG+o], s, s_par[P_BEG+o]);
        cn = cn > 0.0f ? cn : 0.01f*cn;
        op[(size_t)o*HW] = (1.0f-uu)*hcen[o] + uu*cn;
    }
}

// ================= launcher =================
extern "C" void kernel_launch(void* const* d_in, const int* in_sizes, int n_in,
                              void* d_out, int out_size)
{
    const float* f_nodes  = (const float*)d_in[0];
    const float* h_nodes  = (const float*)d_in[1];
    const float* p_nodes  = (const float*)d_in[2];
    const float* w_dmap   = (const float*)d_in[4];
    const float* b_dmap   = (const float*)d_in[5];
    const float* w_decomp = (const float*)d_in[6];
    const float* g_decomp = (const float*)d_in[7];
    const float* be_decomp= (const float*)d_in[8];
    const float* w_cau    = (const float*)d_in[9];
    const float* b_cau    = (const float*)d_in[10];
    const float* w_cal    = (const float*)d_in[11];
    const float* b_cal    = (const float*)d_in[12];
    const float* w_cu     = (const float*)d_in[13];
    const float* g_cu     = (const float*)d_in[14];
    const float* be_cu    = (const float*)d_in[15];
    const float* w_cl     = (const float*)d_in[16];
    const float* g_cl     = (const float*)d_in[17];
    const float* be_cl    = (const float*)d_in[18];
    const float* wg_u     = (const float*)d_in[19];
    const float* bg_u     = (const float*)d_in[20];
    const float* wc_u     = (const float*)d_in[21];
    const float* g_u      = (const float*)d_in[22];
    const float* be_u     = (const float*)d_in[23];
    const float* wg_l     = (const float*)d_in[24];
    const float* bg_l     = (const float*)d_in[25];
    const float* wc_l     = (const float*)d_in[26];
    const float* g_l      = (const float*)d_in[27];
    const float* be_l     = (const float*)d_in[28];

    float* out        = (float*)d_out;
    float* out_decomp = out + (size_t)3*NB*CHW;
    float* out_cmu    = out_decomp + (size_t)NB*3*HW;
    float* out_cml    = out_cmu + (size_t)NB*HW;

    k1_pointwise<<<NB*HW/1024, 256>>>(f_nodes, h_nodes, p_nodes,
                                      w_dmap, b_dmap, w_cau, b_cau, w_cal, b_cal,
                                      w_decomp, w_cu, w_cl,
                                      out_decomp, out_cmu, out_cml, out);

    static int smem_set = 0;
    if (!smem_set){
        cudaFuncSetAttribute(k2_conv, cudaFuncAttributeMaxDynamicSharedMemorySize, SMEM_BYTES);
        smem_set = 1;
    }
    dim3 g2(NW/TILE_W, NH/TILE_H, 2*NB), b2(256, 1, 1);
    k2_conv<<<g2, b2, SMEM_BYTES>>>(h_nodes,
                                    g_decomp, be_decomp,
                                    g_cu, be_cu, g_cl, be_cl,
                                    wg_u, bg_u, wc_u, g_u, be_u,
                                    wg_l, bg_l, wc_l, g_l, be_l,
                                    out);
}

// round 17
// speedup vs baseline: 1.5610x; 1.0150x over previous
#include <cuda_runtime.h>
#include <cuda_bf16.h>
#include <cstdint>

#define NB 8
#define NC 10
#define NH 192
#define NW 192
#define HW (NH*NW)
#define CHW (NC*HW)

// ---------------- k2 geometry ----------------
#define TILE_W 32
#define TILE_H 8
#define TROWP 40              /* tile row words, base gx = x0-4 */
#define TROWS 10              /* 8 + 2 halo */
#define TCI_STRIDE 404        /* padded: tap8 loads conflict-free */
#define TILE_B 16160
#define TILE_CHUNKS 1000

// weight panels: [16 outs x 96 K] bf16, row stride 52 words, conflict-free
#define KPW 52
#define PANEL_SH 1664
#define PANEL_B 3328
#define PANEL_CHUNKS 208

// smem byte layout
#define SM_PANELS 0
#define SM_T0 26624
#define SM_T1 (SM_T0 + TILE_B)
#define SM_T2 (SM_T1 + TILE_B)
#define SM_PAR (SM_T2 + TILE_B)
#define SMEM_BYTES (SM_PAR + 1216)

// param offsets (floats)
#define P_GD 0
#define P_BED 10
#define P_GC 20
#define P_BEC 30
#define P_GG 40
#define P_BEG 50
#define P_WG 60
#define P_BG 100
#define P_WC 102

// ---------------- scratch ----------------
__device__ __align__(16) uint32_t g_a1[NB*CHW];
__device__ __align__(16) uint32_t g_a2[NB*CHW];
__device__ __align__(16) uint32_t g_pm[6*NB*CHW];
__device__ __align__(16) uint32_t g_hp[2*NB*CHW];
__device__ __align__(16) unsigned short g_wp[12*PANEL_SH];

__device__ __forceinline__ float sigmoidf_(float x){ return 1.0f/(1.0f+expf(-x)); }
__device__ __forceinline__ float4 f4fma(float s, float4 v, float4 a){
    return make_float4(fmaf(s,v.x,a.x), fmaf(s,v.y,a.y), fmaf(s,v.z,a.z), fmaf(s,v.w,a.w));
}
__device__ __forceinline__ float4 f4s(float s){ return make_float4(s,s,s,s); }

__device__ __forceinline__ uint32_t smem_to_u32(const void* p) {
    uint32_t a;
    asm("{ .reg .u64 t; cvta.to.shared.u64 t, %1; cvt.u32.u64 %0, t; }" : "=r"(a) : "l"(p));
    return a;
}
#define CP_COMMIT() asm volatile("cp.async.commit_group;")
#define CP_WAIT0()  asm volatile("cp.async.wait_group 0;" ::: "memory")
#define CP_WAIT1()  asm volatile("cp.async.wait_group 1;" ::: "memory")

__device__ __forceinline__ uint32_t packw(float x){
    uint32_t u = __float_as_uint(x);
    float lof = x - __uint_as_float(u & 0xffff0000u);
    __nv_bfloat16 lb = __float2bfloat16(lof);
    unsigned short ls = *(unsigned short*)&lb;
    return (u & 0xffff0000u) | (uint32_t)ls;
}
__device__ __forceinline__ uint4 packw4(float4 v){
    uint4 r;
    r.x = packw(v.x); r.y = packw(v.y); r.z = packw(v.z); r.w = packw(v.w);
    return r;
}

// ================= Kernel 1: pointwise + packing + panel prep + slot0 =================
__global__ __launch_bounds__(256) void k1_pointwise(
    const float* __restrict__ f_nodes,
    const float* __restrict__ h_nodes,
    const float* __restrict__ p_nodes,
    const float* __restrict__ w_dmap, const float* __restrict__ b_dmap,
    const float* __restrict__ w_cau,  const float* __restrict__ b_cau,
    const float* __restrict__ w_cal,  const float* __restrict__ b_cal,
    const float* __restrict__ w_decomp, const float* __restrict__ w_cu, const float* __restrict__ w_cl,
    float* __restrict__ out_decomp, float* __restrict__ out_cmu, float* __restrict__ out_cml,
    float* __restrict__ out_xh)
{
    if (blockIdx.x < 6){
        int s = blockIdx.x;
        const float* w = (s < 2) ? w_decomp : ((s < 4) ? w_cu : w_cl);
        int cibase = (s & 1) * 10;
        for (int i = threadIdx.x; i < PANEL_SH; i += 256){
            int n = i / 104, kk = i - n*104;
            float val = 0.0f;
            if (n < 10 && kk < 96){
                int c = kk >> 4, j = kk & 15;
                int ci = -1, tap = 0;
                if (c < 5){ ci = 2*c + (j >> 3); tap = j & 7; }
                else if (j < 10){ ci = j; tap = 8; }
                if (ci >= 0) val = w[(n*20 + cibase + ci)*9 + tap];
            }
            unsigned u = __float_as_uint(val);
            unsigned short hb = (unsigned short)(u >> 16);
            float lof = val - __uint_as_float(u & 0xffff0000u);
            __nv_bfloat16 lb = __float2bfloat16(lof);
            g_wp[(size_t)(2*s)*PANEL_SH + i]   = hb;
            g_wp[(size_t)(2*s+1)*PANEL_SH + i] = *(unsigned short*)&lb;
        }
    }

    __shared__ float s_wd[90], s_bd[3], s_wcau[40], s_wcal[20], s_bc[2];
    int t = threadIdx.x;
    if (t < 90)              s_wd[t]        = w_dmap[t];
    if (t >= 96 && t < 99)   s_bd[t-96]     = b_dmap[t-96];
    if (t >= 128 && t < 168) s_wcau[t-128]  = w_cau[t-128];
    if (t >= 192 && t < 212) s_wcal[t-192]  = w_cal[t-192];
    if (t == 224) s_bc[0] = b_cau[0];
    if (t == 225) s_bc[1] = b_cal[0];
    __syncthreads();

    int pix = (blockIdx.x*256 + t)*4;
    int b = pix / HW, p = pix - b*HW;

    const float* f1b = f_nodes + (size_t)(1*NB + b)*CHW + p;
    const float* h1b = h_nodes + (size_t)(1*NB + b)*CHW + p;
    const float* h2b = h_nodes + (size_t)(2*NB + b)*CHW + p;

    uint32_t* hp1 = g_hp + (size_t)(0*NB + b)*CHW + p;
    uint32_t* hp2 = g_hp + (size_t)(1*NB + b)*CHW + p;

    float4 f[10];
    float4 dm0 = f4s(s_bd[0]), dm1 = f4s(s_bd[1]), dm2 = f4s(s_bd[2]);
    #pragma unroll
    for (int c=0;c<10;c++){
        f[c]       = *(const float4*)(f1b + c*HW);
        float4 u1  = *(const float4*)(h1b + c*HW);
        float4 u2  = *(const float4*)(h2b + c*HW);
        *(uint4*)(hp1 + c*HW) = packw4(u1);
        *(uint4*)(hp2 + c*HW) = packw4(u2);
        dm0 = f4fma(s_wd[ 0+c],f[c],dm0); dm0 = f4fma(s_wd[10+c],u1,dm0); dm0 = f4fma(s_wd[20+c],u2,dm0);
        dm1 = f4fma(s_wd[30+c],f[c],dm1); dm1 = f4fma(s_wd[40+c],u1,dm1); dm1 = f4fma(s_wd[50+c],u2,dm1);
        dm2 = f4fma(s_wd[60+c],f[c],dm2); dm2 = f4fma(s_wd[70+c],u1,dm2); dm2 = f4fma(s_wd[80+c],u2,dm2);
    }

    float4 att1, att2;
    {
        float d0v[4] = {dm0.x,dm0.y,dm0.z,dm0.w};
        float d1v[4] = {dm1.x,dm1.y,dm1.z,dm1.w};
        float d2v[4] = {dm2.x,dm2.y,dm2.z,dm2.w};
        float a1v[4], a2v[4];
        #pragma unroll
        for (int i=0;i<4;i++){
            float mx = fmaxf(d0v[i], fmaxf(d1v[i], d2v[i]));
            float e0 = expf(d0v[i]-mx), e1 = expf(d1v[i]-mx), e2 = expf(d2v[i]-mx);
            float inv = 1.0f/(e0+e1+e2);
            a1v[i] = e1*inv; a2v[i] = e2*inv;
        }
        att1 = make_float4(a1v[0],a1v[1],a1v[2],a1v[3]);
        att2 = make_float4(a2v[0],a2v[1],a2v[2],a2v[3]);
    }

    uint32_t* a1p = g_a1 + (size_t)b*CHW + p;
    uint32_t* a2p = g_a2 + (size_t)b*CHW + p;
    #pragma unroll
    for (int c=0;c<10;c++){
        *(uint4*)(a1p + c*HW) = packw4(make_float4(f[c].x*att1.x, f[c].y*att1.y, f[c].z*att1.z, f[c].w*att1.w));
        *(uint4*)(a2p + c*HW) = packw4(make_float4(f[c].x*att2.x, f[c].y*att2.y, f[c].z*att2.z, f[c].w*att2.w));
    }

    *(float4*)(out_decomp + (size_t)(b*3+0)*HW + p) = dm0;
    *(float4*)(out_decomp + (size_t)(b*3+1)*HW + p) = dm1;
    *(float4*)(out_decomp + (size_t)(b*3+2)*HW + p) = dm2;

    float4 su = f4s(s_bc[0]);
    #pragma unroll
    for (int j=0;j<4;j++){
        const float* pp = p_nodes + (size_t)((j+1)*NB + b)*CHW + p;
        #pragma unroll
        for (int c=0;c<10;c++) su = f4fma(s_wcau[j*10+c], *(const float4*)(pp + c*HW), su);
    }
    float4 mu = make_float4(sigmoidf_(su.x), sigmoidf_(su.y), sigmoidf_(su.z), sigmoidf_(su.w));
    *(float4*)(out_cmu + (size_t)b*HW + p) = mu;

    float4 sl = f4s(s_bc[1]);
    #pragma unroll
    for (int j=0;j<2;j++){
        const float* pp = p_nodes + (size_t)((j+5)*NB + b)*CHW + p;
        #pragma unroll
        for (int c=0;c<10;c++) sl = f4fma(s_wcal[j*10+c], *(const float4*)(pp + c*HW), sl);
    }
    float4 ml = make_float4(sigmoidf_(sl.x), sigmoidf_(sl.y), sigmoidf_(sl.z), sigmoidf_(sl.w));
    *(float4*)(out_cml + (size_t)b*HW + p) = ml;

    #pragma unroll
    for (int j=0;j<4;j++){
        const float* pp = p_nodes + (size_t)((j+1)*NB + b)*CHW + p;
        uint32_t* od = g_pm + (size_t)(j*NB + b)*CHW + p;
        #pragma unroll
        for (int c=0;c<10;c++){
            float4 v = *(const float4*)(pp + c*HW);
            *(uint4*)(od + c*HW) = packw4(make_float4(v.x*mu.x, v.y*mu.y, v.z*mu.z, v.w*mu.w));
        }
    }
    #pragma unroll
    for (int j=0;j<2;j++){
        const float* pp = p_nodes + (size_t)((j+5)*NB + b)*CHW + p;
        uint32_t* od = g_pm + (size_t)((4+j)*NB + b)*CHW + p;
        #pragma unroll
        for (int c=0;c<10;c++){
            float4 v = *(const float4*)(pp + c*HW);
            *(uint4*)(od + c*HW) = packw4(make_float4(v.x*ml.x, v.y*ml.y, v.z*ml.z, v.w*ml.w));
        }
    }

    const float* h0 = h_nodes + (size_t)b*CHW + p;
    float* o0 = out_xh + (size_t)b*CHW + p;
    #pragma unroll
    for (int c=0;c<10;c++) *(float4*)(o0 + c*HW) = *(const float4*)(h0 + c*HW);
}

// ================= Kernel 2 helpers =================
__device__ __forceinline__ void stage_tile(char* smembase, int toff, const uint32_t* __restrict__ src,
                                           int tid, int x0, int y0)
{
    unsigned sbase = smem_to_u32(smembase + toff);
    #pragma unroll
    for (int j=0;j<4;j++){
        int i = tid + j*256;
        if (i < TILE_CHUNKS){
            int ci = i/100, rem = i - ci*100;
            int r = rem/10, c4 = rem - r*10;
            int gy = y0-1+r, gx = x0-4+c4*4;
            bool in = (gy>=0) & (gy<NH) & (gx>=0) & (gx<NW);
            const uint32_t* g = src + (size_t)ci*HW + (in ? (gy*NW+gx) : 0);
            unsigned d = sbase + (unsigned)((ci*TCI_STRIDE + r*TROWP + c4*4)*4);
            int ssz = in ? 16 : 0;
            asm volatile("cp.async.cg.shared.global [%0], [%1], 16, %2;" :: "r"(d), "l"(g), "r"(ssz));
        }
    }
}

#define PRMT(d, a, b, m) asm("prmt.b32 %0, %1, %2, %3;" : "=r"(d) : "r"(a), "r"(b), "n"(m))

// non-volatile: all deps explicit; ptxas may schedule freely
#define MMA_BF16(c, a0,a1,a2,a3, b0,b1) \
    asm("mma.sync.aligned.m16n8k16.row.col.f32.bf16.bf16.f32 " \
        "{%0,%1,%2,%3}, {%4,%5,%6,%7}, {%8,%9}, {%0,%1,%2,%3};" \
        : "+f"((c)[0]), "+f"((c)[1]), "+f"((c)[2]), "+f"((c)[3]) \
        : "r"(a0), "r"(a1), "r"(a2), "r"(a3), "r"(b0), "r"(b1))

// build main-chunk A fragments for both s
__device__ __forceinline__ void frag_main(uint32_t AH[2][4], uint32_t AL[2][4],
                                          const uint32_t* fe, int off0, int off1)
{
    #pragma unroll
    for (int s=0;s<2;s++){
        const uint32_t* fs = fe + 16*s;
        const uint32_t* fo = fs + TCI_STRIDE;
        uint32_t e0=fs[off0], e1=fs[off1], e2=fs[off0+8], e3=fs[off1+8];
        uint32_t q0=fo[off0], q1=fo[off1], q2=fo[off0+8], q3=fo[off1+8];
        PRMT(AH[s][0], e0, e1, 0x7632); PRMT(AL[s][0], e0, e1, 0x5410);
        PRMT(AH[s][1], e2, e3, 0x7632); PRMT(AL[s][1], e2, e3, 0x5410);
        PRMT(AH[s][2], q0, q1, 0x7632); PRMT(AL[s][2], q0, q1, 0x5410);
        PRMT(AH[s][3], q2, q3, 0x7632); PRMT(AL[s][3], q2, q3, 0x5410);
    }
}

// build tap8-chunk A fragments for both s
__device__ __forceinline__ void frag_tap8(uint32_t AH[2][4], uint32_t AL[2][4],
                                          const uint32_t* f8, int t)
{
    #pragma unroll
    for (int s=0;s<2;s++){
        const uint32_t* fs = f8 + 16*s;
        uint32_t e0 = fs[(2*t)*TCI_STRIDE],   e1 = fs[(2*t+1)*TCI_STRIDE];
        uint32_t e2 = fs[(2*t)*TCI_STRIDE+8], e3 = fs[(2*t+1)*TCI_STRIDE+8];
        PRMT(AH[s][0], e0, e1, 0x7632); PRMT(AL[s][0], e0, e1, 0x5410);
        PRMT(AH[s][1], e2, e3, 0x7632); PRMT(AL[s][1], e2, e3, 0x5410);
        AH[s][2]=0u; AL[s][2]=0u; AH[s][3]=0u; AL[s][3]=0u;
        if (t == 0){
            uint32_t r0 = fs[8*TCI_STRIDE],   r1 = fs[9*TCI_STRIDE];
            uint32_t r2 = fs[8*TCI_STRIDE+8], r3 = fs[9*TCI_STRIDE+8];
            PRMT(AH[s][2], r0, r1, 0x7632); PRMT(AL[s][2], r0, r1, 0x5410);
            PRMT(AH[s][3], r2, r3, 0x7632); PRMT(AL[s][3], r2, r3, 0x5410);
        }
    }
}

// term-major MMA issue: dep distance 4
#define ISSUE_TERMS(C, AH, AL, bh0, bh1, bl0, bl1) do { \
    _Pragma("unroll") for (int s=0;s<2;s++) _Pragma("unroll") for (int n=0;n<2;n++) \
        MMA_BF16(C[s][n], AH[s][0],AH[s][1],AH[s][2],AH[s][3], bh0[n], bh1[n]); \
    _Pragma("unroll") for (int s=0;s<2;s++) _Pragma("unroll") for (int n=0;n<2;n++) \
        MMA_BF16(C[s][n], AL[s][0],AL[s][1],AL[s][2],AL[s][3], bh0[n], bh1[n]); \
    _Pragma("unroll") for (int s=0;s<2;s++) _Pragma("unroll") for (int n=0;n<2;n++) \
        MMA_BF16(C[s][n], AH[s][0],AH[s][1],AH[s][2],AH[s][3], bl0[n], bl1[n]); \
} while(0)

// term-major across two accumulator sets: dep distance 8
#define ISSUE_TERMS2(C1, C2, AH, AL, b1h0,b1h1,b1l0,b1l1, b2h0,b2h1,b2l0,b2l1) do { \
    _Pragma("unroll") for (int s=0;s<2;s++) _Pragma("unroll") for (int n=0;n<2;n++){ \
        MMA_BF16(C1[s][n], AH[s][0],AH[s][1],AH[s][2],AH[s][3], b1h0[n], b1h1[n]); \
        MMA_BF16(C2[s][n], AH[s][0],AH[s][1],AH[s][2],AH[s][3], b2h0[n], b2h1[n]); } \
    _Pragma("unroll") for (int s=0;s<2;s++) _Pragma("unroll") for (int n=0;n<2;n++){ \
        MMA_BF16(C1[s][n], AL[s][0],AL[s][1],AL[s][2],AL[s][3], b1h0[n], b1h1[n]); \
        MMA_BF16(C2[s][n], AL[s][0],AL[s][1],AL[s][2],AL[s][3], b2h0[n], b2h1[n]); } \
    _Pragma("unroll") for (int s=0;s<2;s++) _Pragma("unroll") for (int n=0;n<2;n++){ \
        MMA_BF16(C1[s][n], AH[s][0],AH[s][1],AH[s][2],AH[s][3], b1l0[n], b1l1[n]); \
        MMA_BF16(C2[s][n], AH[s][0],AH[s][1],AH[s][2],AH[s][3], b2l0[n], b2l1[n]); } \
} while(0)

__device__ __forceinline__ void conv_hmma(
    float C[2][2][4], const uint32_t* tile,
    const uint32_t* ph, const uint32_t* pl,
    int w, int g, int t, int off0, int off1)
{
    #pragma unroll 1
    for (int c=0; c<5; c++){
        uint32_t bh0[2], bh1[2], bl0[2], bl1[2];
        #pragma unroll
        for (int n=0;n<2;n++){
            int bi = (n*8+g)*KPW + c*8 + t;
            bh0[n]=ph[bi]; bh1[n]=ph[bi+4];
            bl0[n]=pl[bi]; bl1[n]=pl[bi+4];
        }
        uint32_t AH[2][4], AL[2][4];
        frag_main(AH, AL, tile + (2*c)*TCI_STRIDE + w*TROWP + g + 3, off0, off1);
        ISSUE_TERMS(C, AH, AL, bh0, bh1, bl0, bl1);
    }
    {
        uint32_t bh0[2], bh1[2], bl0[2], bl1[2];
        #pragma unroll
        for (int n=0;n<2;n++){
            int bi = (n*8+g)*KPW + 40 + t;
            bh0[n]=ph[bi]; bh1[n]=ph[bi+4];
            bl0[n]=pl[bi]; bl1[n]=pl[bi+4];
        }
        uint32_t AH[2][4], AL[2][4];
        frag_tap8(AH, AL, tile + w*TROWP + g + 3 + 2*TROWP + 2, t);
        ISSUE_TERMS(C, AH, AL, bh0, bh1, bl0, bl1);
    }
}

__device__ __forceinline__ void conv_hmma_dual(
    float C1[2][2][4], float C2[2][2][4], const uint32_t* tile,
    const uint32_t* p1h, const uint32_t* p1l,
    const uint32_t* p2h, const uint32_t* p2l,
    int w, int g, int t, int off0, int off1)
{
    #pragma unroll 1
    for (int c=0; c<5; c++){
        uint32_t b1h0[2], b1h1[2], b1l0[2], b1l1[2];
        uint32_t b2h0[2], b2h1[2], b2l0[2], b2l1[2];
        #pragma unroll
        for (int n=0;n<2;n++){
            int bi = (n*8+g)*KPW + c*8 + t;
            b1h0[n]=p1h[bi]; b1h1[n]=p1h[bi+4];
            b1l0[n]=p1l[bi]; b1l1[n]=p1l[bi+4];
            b2h0[n]=p2h[bi]; b2h1[n]=p2h[bi+4];
            b2l0[n]=p2l[bi]; b2l1[n]=p2l[bi+4];
        }
        uint32_t AH[2][4], AL[2][4];
        frag_main(AH, AL, tile + (2*c)*TCI_STRIDE + w*TROWP + g + 3, off0, off1);
        ISSUE_TERMS2(C1, C2, AH, AL, b1h0,b1h1,b1l0,b1l1, b2h0,b2h1,b2l0,b2l1);
    }
    {
        uint32_t b1h0[2], b1h1[2], b1l0[2], b1l1[2];
        uint32_t b2h0[2], b2h1[2], b2l0[2], b2l1[2];
        #pragma unroll
        for (int n=0;n<2;n++){
            int bi = (n*8+g)*KPW + 40 + t;
            b1h0[n]=p1h[bi]; b1h1[n]=p1h[bi+4];
            b1l0[n]=p1l[bi]; b1l1[n]=p1l[bi+4];
            b2h0[n]=p2h[bi]; b2h1[n]=p2h[bi+4];
            b2l0[n]=p2l[bi]; b2l1[n]=p2l[bi+4];
        }
        uint32_t AH[2][4], AL[2][4];
        frag_tap8(AH, AL, tile + w*TROWP + g + 3 + 2*TROWP + 2, t);
        ISSUE_TERMS2(C1, C2, AH, AL, b1h0,b1h1,b1l0,b1l1, b2h0,b2h1,b2l0,b2l1);
    }
}

// ================= Kernel 2: HMMA fused convs + GRU =================
__global__ __launch_bounds__(256,2) void k2_conv(
    const float* __restrict__ h_nodes,
    const float* __restrict__ g_decomp, const float* __restrict__ be_decomp,
    const float* __restrict__ g_cu, const float* __restrict__ be_cu,
    const float* __restrict__ g_cl, const float* __restrict__ be_cl,
    const float* __restrict__ wg_u, const float* __restrict__ bg_u,
    const float* __restrict__ wc_u, const float* __restrict__ g_u, const float* __restrict__ be_u,
    const float* __restrict__ wg_l, const float* __restrict__ bg_l,
    const float* __restrict__ wc_l, const float* __restrict__ g_l, const float* __restrict__ be_l,
    float* __restrict__ out_xh)
{
    extern __shared__ __align__(16) char smem[];
    float* s_par = (float*)(smem + SM_PAR);

    int z = blockIdx.z; int b = z >> 1; int half = z & 1;
    const float* gcv  = half ? g_cl  : g_cu;
    const float* becv = half ? be_cl : be_cu;
    const uint32_t* aX  = (half ? g_a2 : g_a1) + (size_t)b*CHW;
    const uint32_t* hpX = g_hp + (size_t)(half*NB + b)*CHW;
    const float* hX   = h_nodes + (size_t)((half?2:1)*NB + b)*CHW;
    const float* wgv  = half ? wg_l : wg_u;
    const float* bgv  = half ? bg_l : bg_u;
    const float* wcv  = half ? wc_l : wc_u;
    const float* ggv  = half ? g_l  : g_u;
    const float* bev  = half ? be_l : be_u;
    float* outp       = out_xh + (size_t)((half?2:1)*NB + b)*CHW;
    int nparts = half ? 2 : 4;
    int pidx0  = half ? 4 : 0;

    int tid = threadIdx.x;
    int w = tid >> 5, lane = tid & 31;
    int g = lane >> 2, t = lane & 3;
    int x0 = blockIdx.x*TILE_W, y0 = blockIdx.y*TILE_H;

    int tp0 = 2*t, tp1 = 2*t+1;
    int dy0 = tp0/3, dx0 = tp0 - 3*dy0;
    int dy1 = tp1/3, dx1 = tp1 - 3*dy1;
    int off0 = dy0*TROWP + dx0, off1 = dy1*TROWP + dx1;

    // ---- issue panel + a/h tile cp.async (one group) ----
    {
        unsigned sb = smem_to_u32(smem);
        #pragma unroll
        for (int j=0;j<7;j++){
            int i = tid + j*256;
            if (i < 8*PANEL_CHUNKS){
                int lp = i / PANEL_CHUNKS, within = i - lp*PANEL_CHUNKS;
                int gp = (lp < 4) ? lp : ((half ? 8 : 4) + (lp-4));
                const char* gsrc = (const char*)g_wp + (size_t)gp*PANEL_B + within*16;
                unsigned d = sb + (unsigned)(SM_PANELS + lp*PANEL_B + within*16);
                asm volatile("cp.async.cg.shared.global [%0], [%1], 16;" :: "r"(d), "l"(gsrc));
            }
        }
        stage_tile(smem, SM_T0, aX, tid, x0, y0);
        stage_tile(smem, SM_T1, hpX, tid, x0, y0);
        CP_COMMIT();
    }

    // ---- params ----
    if (tid < 10){
        s_par[P_GD+tid]=g_decomp[tid]; s_par[P_BED+tid]=be_decomp[tid];
        s_par[P_GC+tid]=gcv[tid];      s_par[P_BEC+tid]=becv[tid];
        s_par[P_GG+tid]=ggv[tid];      s_par[P_BEG+tid]=bev[tid];
    }
    if (tid >= 32 && tid < 72) s_par[P_WG + tid-32] = wgv[tid-32];
    if (tid == 72) { s_par[P_BG]=bgv[0]; s_par[P_BG+1]=bgv[1]; }
    if (tid < 100){ s_par[P_WC+tid] = wcv[tid]; s_par[P_WC+100+tid] = wcv[100+tid]; }

    CP_WAIT0();
    __syncthreads();

    // issue part0 -> T2
    stage_tile(smem, SM_T2, g_pm + (size_t)(pidx0*NB + b)*CHW, tid, x0, y0);
    CP_COMMIT();

    const uint32_t* pan = (const uint32_t*)(smem + SM_PANELS);
    const uint32_t* p_wdta_h = pan + 0*(PANEL_B/4);
    const uint32_t* p_wdta_l = pan + 1*(PANEL_B/4);
    const uint32_t* p_wdth_h = pan + 2*(PANEL_B/4);
    const uint32_t* p_wdth_l = pan + 3*(PANEL_B/4);
    const uint32_t* p_wcth_h = pan + 4*(PANEL_B/4);
    const uint32_t* p_wcth_l = pan + 5*(PANEL_B/4);
    const uint32_t* p_wctp_h = pan + 6*(PANEL_B/4);
    const uint32_t* p_wctp_l = pan + 7*(PANEL_B/4);

    int o0 = 2*t, o1 = 2*t+1, o8 = 8+2*t, o9 = 9+2*t;
    float gd_[4]  = { s_par[P_GD+o0],  s_par[P_GD+o1],  s_par[P_GD+o8],  s_par[P_GD+o9]  };
    float bed_[4] = { s_par[P_BED+o0], s_par[P_BED+o1], s_par[P_BED+o8], s_par[P_BED+o9] };
    float gc_[4]  = { s_par[P_GC+o0],  s_par[P_GC+o1],  s_par[P_GC+o8],  s_par[P_GC+o9]  };
    float bec_[4] = { s_par[P_BEC+o0], s_par[P_BEC+o1], s_par[P_BEC+o8], s_par[P_BEC+o9] };

    // ---- a-tile conv ----
    float Dd[2][2][4];
    #pragma unroll
    for (int s=0;s<2;s++)
        #pragma unroll
        for (int n=0;n<2;n++)
            #pragma unroll
            for (int j=0;j<4;j++) Dd[s][n][j] = 0.0f;
    conv_hmma(Dd, (const uint32_t*)(smem + SM_T0), p_wdta_h, p_wdta_l, w, g, t, off0, off1);

    // ---- h-tile dual conv ----
    float accA[2][2][4];
    #pragma unroll
    for (int s=0;s<2;s++)
        #pragma unroll
        for (int n=0;n<2;n++)
            #pragma unroll
            for (int j=0;j<4;j++) accA[s][n][j] = 0.0f;
    conv_hmma_dual(Dd, accA, (const uint32_t*)(smem + SM_T1),
                   p_wdth_h, p_wdth_l, p_wcth_h, p_wcth_l, w, g, t, off0, off1);

    #pragma unroll
    for (int s=0;s<2;s++)
        #pragma unroll
        for (int n=0;n<2;n++)
            #pragma unroll
            for (int j=0;j<4;j++){
                int oi = n*2 + (j&1);
                Dd[s][n][j] = fmaxf(fmaf(gd_[oi], Dd[s][n][j], bed_[oi]), 0.0f);
            }

    __syncthreads();

    // ---- part loop (ring T2,T0,T1) ----
    const int bufoff[3] = {SM_T2, SM_T0, SM_T1};
    for (int part=0; part<nparts; part++){
        if (part+1 < nparts){
            stage_tile(smem, bufoff[(part+1)%3], g_pm + (size_t)((pidx0+part+1)*NB + b)*CHW, tid, x0, y0);
            CP_COMMIT();
            CP_WAIT1();
        } else {
            CP_WAIT0();
        }
        __syncthreads();

        float Cp[2][2][4];
        #pragma unroll
        for (int s=0;s<2;s++)
            #pragma unroll
            for (int n=0;n<2;n++)
                #pragma unroll
                for (int j=0;j<4;j++) Cp[s][n][j] = accA[s][n][j];
        conv_hmma(Cp, (const uint32_t*)(smem + bufoff[part%3]), p_wctp_h, p_wctp_l, w, g, t, off0, off1);
        #pragma unroll
        for (int s=0;s<2;s++)
            #pragma unroll
            for (int n=0;n<2;n++)
                #pragma unroll
                for (int j=0;j<4;j++){
                    int oi = n*2 + (j&1);
                    Dd[s][n][j] += fmaxf(fmaf(gc_[oi], Cp[s][n][j], bec_[oi]), 0.0f);
                }
    }

    // ---- scatter msg fragments to smem (reuse T0) ----
    __syncthreads();
    float* s_msg = (float*)(smem + SM_T0);
    #pragma unroll
    for (int s=0;s<2;s++){
        int m0 = w*32 + s*16 + g;
        #pragma unroll
        for (int n=0;n<2;n++){
            if (n == 0 || t == 0){
                int oc = n*8 + 2*t;
                *(float2*)&s_msg[m0*12 + oc]     = make_float2(Dd[s][n][0], Dd[s][n][1]);
                *(float2*)&s_msg[(m0+8)*12 + oc] = make_float2(Dd[s][n][2], Dd[s][n][3]);
            }
        }
    }
    __syncthreads();

    // ---------- GRU epilogue (1 px per thread) ----------
    int py = y0 + (tid >> 5), pxx = x0 + (tid & 31);
    float msg[10], hcen[10];
    #pragma unroll
    for (int c=0;c<10;c++) msg[c] = s_msg[tid*12 + c];
    {
        const float* hc = hX + (size_t)py*NW + pxx;
        #pragma unroll
        for (int c=0;c<10;c++) hcen[c] = hc[(size_t)c*HW];
    }
    float g0 = s_par[P_BG], g1 = s_par[P_BG+1];
    #pragma unroll
    for (int c=0;c<10;c++){
        g0 = fmaf(s_par[P_WG+c],    msg[c],  g0);
        g0 = fmaf(s_par[P_WG+10+c], hcen[c], g0);
        g1 = fmaf(s_par[P_WG+20+c], msg[c],  g1);
        g1 = fmaf(s_par[P_WG+30+c], hcen[c], g1);
    }
    float rr = sigmoidf_(g0), uu = sigmoidf_(g1);
    float rh[10];
    #pragma unroll
    for (int c=0;c<10;c++) rh[c] = rr*hcen[c];

    float* op = outp + (size_t)py*NW + pxx;
    #pragma unroll
    for (int o=0;o<10;o++){
        float s = 0.0f;
        #pragma unroll
        for (int c=0;c<10;c++){
            s = fmaf(s_par[P_WC + o*20 + c],      msg[c], s);
            s = fmaf(s_par[P_WC + o*20 + 10 + c], rh[c],  s);
        }
        float cn = fmaf(s_par[P_GG+o], s, s_par[P_BEG+o]);
        cn = cn > 0.0f ? cn : 0.01f*cn;
        op[(size_t)o*HW] = (1.0f-uu)*hcen[o] + uu*cn;
    }
}

// ================= launcher =================
extern "C" void kernel_launch(void* const* d_in, const int* in_sizes, int n_in,
                              void* d_out, int out_size)
{
    const float* f_nodes  = (const float*)d_in[0];
    const float* h_nodes  = (const float*)d_in[1];
    const float* p_nodes  = (const float*)d_in[2];
    const float* w_dmap   = (const float*)d_in[4];
    const float* b_dmap   = (const float*)d_in[5];
    const float* w_decomp = (const float*)d_in[6];
    const float* g_decomp = (const float*)d_in[7];
    const float* be_decomp= (const float*)d_in[8];
    const float* w_cau    = (const float*)d_in[9];
    const float* b_cau    = (const float*)d_in[10];
    const float* w_cal    = (const float*)d_in[11];
    const float* b_cal    = (const float*)d_in[12];
    const float* w_cu     = (const float*)d_in[13];
    const float* g_cu     = (const float*)d_in[14];
    const float* be_cu    = (const float*)d_in[15];
    const float* w_cl     = (const float*)d_in[16];
    const float* g_cl     = (const float*)d_in[17];
    const float* be_cl    = (const float*)d_in[18];
    const float* wg_u     = (const float*)d_in[19];
    const float* bg_u     = (const float*)d_in[20];
    const float* wc_u     = (const float*)d_in[21];
    const float* g_u      = (const float*)d_in[22];
    const float* be_u     = (const float*)d_in[23];
    const float* wg_l     = (const float*)d_in[24];
    const float* bg_l     = (const float*)d_in[25];
    const float* wc_l     = (const float*)d_in[26];
    const float* g_l      = (const float*)d_in[27];
    const float* be_l     = (const float*)d_in[28];

    float* out        = (float*)d_out;
    float* out_decomp = out + (size_t)3*NB*CHW;
    float* out_cmu    = out_decomp + (size_t)NB*3*HW;
    float* out_cml    = out_cmu + (size_t)NB*HW;

    k1_pointwise<<<NB*HW/1024, 256>>>(f_nodes, h_nodes, p_nodes,
                                      w_dmap, b_dmap, w_cau, b_cau, w_cal, b_cal,
                                      w_decomp, w_cu, w_cl,
                                      out_decomp, out_cmu, out_cml, out);

    static int smem_set = 0;
    if (!smem_set){
        cudaFuncSetAttribute(k2_conv, cudaFuncAttributeMaxDynamicSharedMemorySize, SMEM_BYTES);
        smem_set = 1;
    }
    dim3 g2(NW/TILE_W, NH/TILE_H, 2*NB), b2(256, 1, 1);
    k2_conv<<<g2, b2, SMEM_BYTES>>>(h_nodes,
                                    g_decomp, be_decomp,
                                    g_cu, be_cu, g_cl, be_cl,
                                    wg_u, bg_u, wc_u, g_u, be_u,
                                    wg_l, bg_l, wc_l, g_l, be_l,
                                    out);
}